// round 4
// baseline (speedup 1.0000x reference)
#include <cuda_runtime.h>
#include <cuda_bf16.h>
#include <math.h>
#include <cstdint>

// Problem constants (fixed by the dataset)
#define NN   20000
#define NE   320000
#define DIN  50
#define HID  1024
#define F3   726        // 6 heads * 121 classes
#define NCLS 121
#define N2   2048       // W2 || S2 concatenated output width
#define N3   1452       // W3 || S3 concatenated output width

// ---------------- scratch (device globals) -------------------------------------
__device__ __align__(128) float g_A[(size_t)NN * N2];    // 164 MB (widest output)
__device__ __align__(128) float g_F[(size_t)NN * HID];   // 82 MB
__device__ __align__(128) __nv_bfloat16 g_Ah[(size_t)NN * HID];
__device__ __align__(128) __nv_bfloat16 g_Al[(size_t)NN * HID];
__device__ __align__(128) __nv_bfloat16 g_W2h[(size_t)N2 * HID];
__device__ __align__(128) __nv_bfloat16 g_W2l[(size_t)N2 * HID];
__device__ __align__(128) __nv_bfloat16 g_W3h[(size_t)N3 * HID];
__device__ __align__(128) __nv_bfloat16 g_W3l[(size_t)N3 * HID];
__device__ int   g_deg[NN];
__device__ int   g_cursor[NN];
__device__ int   g_offs[NN + 1];
__device__ int   g_src[NE];
__device__ float g_w[NE];

// ================= PTX helpers (portable sm_80+ PTX) ===========================
__device__ __forceinline__ uint32_t smem_u32(const void* p) {
    uint32_t a;
    asm("{ .reg .u64 t; cvta.to.shared.u64 t, %1; cvt.u32.u64 %0, t; }" : "=r"(a) : "l"(p));
    return a;
}
__device__ __forceinline__ void cp16(uint32_t dst, const void* src) {
    uint64_t g = __cvta_generic_to_global(src);
    asm volatile("cp.async.cg.shared.global [%0], [%1], 16;" :: "r"(dst), "l"(g));
}
__device__ __forceinline__ void cp_commit() { asm volatile("cp.async.commit_group;" ::: "memory"); }
template <int N> __device__ __forceinline__ void cp_wait() {
    asm volatile("cp.async.wait_group %0;" :: "n"(N) : "memory");
}
__device__ __forceinline__ void ldm_x4(uint32_t* r, uint32_t addr) {
    asm volatile("ldmatrix.sync.aligned.m8n8.x4.shared.b16 {%0,%1,%2,%3}, [%4];"
                 : "=r"(r[0]), "=r"(r[1]), "=r"(r[2]), "=r"(r[3]) : "r"(addr));
}
__device__ __forceinline__ void ldm_x2(uint32_t* r, uint32_t addr) {
    asm volatile("ldmatrix.sync.aligned.m8n8.x2.shared.b16 {%0,%1}, [%2];"
                 : "=r"(r[0]), "=r"(r[1]) : "r"(addr));
}
__device__ __forceinline__ void mma16816(float* c, const uint32_t* a, const uint32_t* b) {
    asm volatile(
        "mma.sync.aligned.m16n8k16.row.col.f32.bf16.bf16.f32 "
        "{%0,%1,%2,%3}, {%4,%5,%6,%7}, {%8,%9}, {%0,%1,%2,%3};"
        : "+f"(c[0]), "+f"(c[1]), "+f"(c[2]), "+f"(c[3])
        : "r"(a[0]), "r"(a[1]), "r"(a[2]), "r"(a[3]), "r"(b[0]), "r"(b[1]));
}

// ---------------- prep: zero deg/cursor + transpose/split all weights ----------
__global__ void prep_kernel(const float* __restrict__ W2, const float* __restrict__ S2,
                            const float* __restrict__ W3, const float* __restrict__ S3,
                            __nv_bfloat16* __restrict__ W2h, __nv_bfloat16* __restrict__ W2l,
                            __nv_bfloat16* __restrict__ W3h, __nv_bfloat16* __restrict__ W3l,
                            int* __restrict__ deg, int* __restrict__ cur) {
    int i = blockIdx.x * blockDim.x + threadIdx.x;
    int stride = gridDim.x * blockDim.x;
    if (i < NN) { deg[i] = 0; cur[i] = 0; }
    for (int j = i; j < N2 * HID; j += stride) {
        int n = j >> 10, k = j & 1023;
        float v = (n < HID) ? W2[(size_t)k * HID + n] : S2[(size_t)k * HID + (n - HID)];
        __nv_bfloat16 h = __float2bfloat16(v);
        W2h[j] = h;
        W2l[j] = __float2bfloat16(v - __bfloat162float(h));
    }
    for (int j = i; j < N3 * HID; j += stride) {
        int n = j >> 10, k = j & 1023;
        float v = (n < F3) ? W3[(size_t)k * F3 + n] : S3[(size_t)k * F3 + (n - F3)];
        __nv_bfloat16 h = __float2bfloat16(v);
        W3h[j] = h;
        W3l[j] = __float2bfloat16(v - __bfloat162float(h));
    }
}

// ---------------- CSR build ------------------------------------------------------
__global__ void count_deg_kernel(const int* __restrict__ col, int* __restrict__ deg) {
    for (int e = blockIdx.x * blockDim.x + threadIdx.x; e < NE; e += gridDim.x * blockDim.x)
        atomicAdd(&deg[col[e]], 1);
}

__global__ void scan_kernel(const int* __restrict__ counts, int* __restrict__ offs) {
    __shared__ int sm[1024];
    __shared__ int carry_s;
    if (threadIdx.x == 0) carry_s = 0;
    __syncthreads();
    for (int base = 0; base < NN; base += 1024) {
        int i = base + threadIdx.x;
        int v = (i < NN) ? counts[i] : 0;
        sm[threadIdx.x] = v;
        __syncthreads();
        for (int off = 1; off < 1024; off <<= 1) {
            int t = (threadIdx.x >= off) ? sm[threadIdx.x - off] : 0;
            __syncthreads();
            sm[threadIdx.x] += t;
            __syncthreads();
        }
        int c0 = carry_s;
        if (i < NN) offs[i] = c0 + sm[threadIdx.x] - v;
        int total = sm[1023];
        __syncthreads();
        if (threadIdx.x == 0) carry_s = c0 + total;
        __syncthreads();
    }
    if (threadIdx.x == 0) offs[NN] = carry_s;
}

__global__ void fill_csr_kernel(const int* __restrict__ row, const int* __restrict__ col,
                                const int* __restrict__ offs, int* __restrict__ cursor,
                                const int* __restrict__ deg,
                                int* __restrict__ csr_src, float* __restrict__ csr_w) {
    for (int e = blockIdx.x * blockDim.x + threadIdx.x; e < NE; e += gridDim.x * blockDim.x) {
        int r = row[e], c = col[e];
        int p = atomicAdd(&cursor[c], 1);
        int slot = offs[c] + p;
        int dr = deg[r];
        float nr = (dr > 0) ? rsqrtf((float)dr) : 0.0f;
        float nc = rsqrtf((float)deg[c]);   // deg[c] >= 1 (this edge)
        csr_src[slot] = r;
        csr_w[slot] = nr * nc;
    }
}

// ---------------- layer-1 GEMM: X[N,50] @ W1[50,1024] -------------------------
__global__ void gemm1_kernel(const float* __restrict__ X, const float* __restrict__ W,
                             float* __restrict__ out) {
    __shared__ float Ws[DIN][128];
    __shared__ float Xs[16][DIN + 2];
    int t = threadIdx.x;
    int j0 = blockIdx.y * 128;
    int n0 = blockIdx.x * 16;
    for (int k = 0; k < DIN; k++) Ws[k][t] = W[(size_t)k * HID + j0 + t];
    for (int i = t; i < 16 * DIN; i += 128) {
        int nn = i / DIN, k = i % DIN;
        Xs[nn][k] = (n0 + nn < NN) ? X[(size_t)(n0 + nn) * DIN + k] : 0.0f;
    }
    __syncthreads();
    #pragma unroll 4
    for (int nn = 0; nn < 16; nn++) {
        float acc = 0.f;
        #pragma unroll
        for (int k = 0; k < DIN; k++) acc = fmaf(Xs[nn][k], Ws[k][t], acc);
        if (n0 + nn < NN) out[(size_t)(n0 + nn) * HID + j0 + t] = acc;
    }
}

// ---------------- mma.sync GEMM (KC=64, double buffered) -----------------------
// C[M, Nn] = A[M, 1024] * B^T, B stored [Nn][1024]. D += Ah*Bh + Ah*Bl + Al*Bh.
#define KC    64
#define NCH   (HID / KC)        // 16 chunks
#define RS    144               // 128B data + 16B pad per row
#define ARR_B (128 * RS)        // 18432
#define STG_B (4 * ARR_B)       // 73728
#define MMA_SMEM (2 * STG_B)    // 147456

__device__ __forceinline__ void mma_load_chunk(
    uint32_t st, int k0,
    const __nv_bfloat16* __restrict__ Ah, const __nv_bfloat16* __restrict__ Al,
    const __nv_bfloat16* __restrict__ Bh, const __nv_bfloat16* __restrict__ Bl,
    int tid, int m0, int n0, int M, int Nn) {
    const __nv_bfloat16* bases[4] = {Ah, Al, Bh, Bl};
    int rrow = tid >> 1;           // 0..127
    int half = tid & 1;            // 64B half of row
    #pragma unroll
    for (int arr = 0; arr < 4; arr++) {
        int g0  = (arr < 2) ? m0 : n0;
        int lim = (arr < 2) ? M  : Nn;
        int grow = g0 + rrow;
        if (grow < lim) {
            const __nv_bfloat16* gp = bases[arr] + (size_t)grow * HID + k0 + half * 32;
            uint32_t sa = st + arr * ARR_B + rrow * RS + half * 64;
            #pragma unroll
            for (int q = 0; q < 4; q++) cp16(sa + q * 16, gp + q * 8);
        }
    }
    cp_commit();
}

__global__ void __launch_bounds__(256, 1) mma_gemm_kernel(
    const __nv_bfloat16* __restrict__ Ah, const __nv_bfloat16* __restrict__ Al,
    const __nv_bfloat16* __restrict__ Bh, const __nv_bfloat16* __restrict__ Bl,
    float* __restrict__ Cc, int M, int Nn) {
    extern __shared__ char smem[];
    uint32_t sb = smem_u32(smem);
    int tid = threadIdx.x;
    int wid = tid >> 5, lane = tid & 31;
    int wm = wid >> 2, wn = wid & 3;             // 2 x 4 warp grid
    int m0 = blockIdx.y * 128;
    int n0 = blockIdx.x * 128;

    // zero-fill rows never cp'd (edge tiles), both stages
    if (m0 + 128 > M || n0 + 128 > Nn) {
        for (int e = tid; e < 1024; e += 256) {
            int s = e >> 9, rem = e & 511;
            int arr = rem >> 7, r = rem & 127;
            bool valid = (arr < 2) ? (m0 + r < M) : (n0 + r < Nn);
            if (!valid) {
                uint32_t a = sb + s * STG_B + arr * ARR_B + r * RS;
                #pragma unroll
                for (int q = 0; q < 9; q++)
                    asm volatile("st.shared.v4.b32 [%0], {%1, %1, %1, %1};"
                                 :: "r"(a + q * 16), "r"(0u) : "memory");
            }
        }
        __syncthreads();
    }

    float acc[4][4][4];
    #pragma unroll
    for (int i = 0; i < 4; i++)
        #pragma unroll
        for (int j = 0; j < 4; j++)
            #pragma unroll
            for (int q = 0; q < 4; q++) acc[i][j][q] = 0.f;

    mma_load_chunk(sb, 0, Ah, Al, Bh, Bl, tid, m0, n0, M, Nn);

    int la = lane & 15, lha = (lane >> 4) & 1;
    int lb = lane & 7,  lhb = (lane >> 3) & 1;

    for (int i = 0; i < NCH; i++) {
        int b = i & 1;
        if (i + 1 < NCH) {
            mma_load_chunk(sb + (b ^ 1) * STG_B, (i + 1) * KC, Ah, Al, Bh, Bl,
                           tid, m0, n0, M, Nn);
            cp_wait<1>();
        } else {
            cp_wait<0>();
        }
        __syncthreads();

        uint32_t st = sb + b * STG_B;
        uint32_t aB = st + (wm * 64) * RS;
        uint32_t bB = st + 2 * ARR_B + (wn * 32) * RS;

        #pragma unroll
        for (int kk = 0; kk < 4; kk++) {
            uint32_t ah[4][4], al[4][4], bh[4][2], bl[4][2];
            #pragma unroll
            for (int im = 0; im < 4; im++) {
                uint32_t ad = aB + (im * 16 + la) * RS + lha * 16 + kk * 32;
                ldm_x4(ah[im], ad);
                ldm_x4(al[im], ad + ARR_B);
            }
            #pragma unroll
            for (int in = 0; in < 4; in++) {
                uint32_t bd = bB + (in * 8 + lb) * RS + lhb * 16 + kk * 32;
                ldm_x2(bh[in], bd);
                ldm_x2(bl[in], bd + ARR_B);
            }
            #pragma unroll
            for (int im = 0; im < 4; im++)
                #pragma unroll
                for (int in = 0; in < 4; in++) {
                    mma16816(acc[im][in], ah[im], bh[in]);
                    mma16816(acc[im][in], ah[im], bl[in]);
                    mma16816(acc[im][in], al[im], bh[in]);
                }
        }
        __syncthreads();
    }

    // epilogue
    int cm = m0 + wm * 64 + (lane >> 2);
    int cn0 = n0 + wn * 32 + (lane & 3) * 2;
    #pragma unroll
    for (int im = 0; im < 4; im++) {
        int r0 = cm + im * 16;
        #pragma unroll
        for (int in = 0; in < 4; in++) {
            int c = cn0 + in * 8;
            if (c < Nn) {   // Nn even, c even -> c+1 valid too
                if (r0 < M) {
                    float2 v = make_float2(acc[im][in][0], acc[im][in][1]);
                    *(float2*)(Cc + (size_t)r0 * Nn + c) = v;
                }
                if (r0 + 8 < M) {
                    float2 v = make_float2(acc[im][in][2], acc[im][in][3]);
                    *(float2*)(Cc + (size_t)(r0 + 8) * Nn + c) = v;
                }
            }
        }
    }
}

// ---------------- aggregation + elu + bf16 split (fused) ------------------------
__device__ __forceinline__ float elu_f(float x) {
    return x > 0.f ? x : (expf(x) - 1.f);
}

// 1024 features: acc = agg(src rows, stride) [+ skip], elu, write bf16 hi/lo
__global__ void agg_split_kernel(const float* __restrict__ src, const float* __restrict__ skip,
                                 int stride,
                                 __nv_bfloat16* __restrict__ oh, __nv_bfloat16* __restrict__ ol,
                                 const int* __restrict__ offs, const int* __restrict__ csr_src,
                                 const float* __restrict__ csr_w) {
    int node = blockIdx.x;
    int tid = threadIdx.x;
    float4 acc = make_float4(0.f, 0.f, 0.f, 0.f);
    int beg = offs[node], end = offs[node + 1];
    for (int j = beg; j < end; j++) {
        int s = csr_src[j];
        float w = csr_w[j];
        float4 v = __ldg((const float4*)(src + (size_t)s * stride) + tid);
        acc.x = fmaf(w, v.x, acc.x);
        acc.y = fmaf(w, v.y, acc.y);
        acc.z = fmaf(w, v.z, acc.z);
        acc.w = fmaf(w, v.w, acc.w);
    }
    if (skip) {
        float4 sv = ((const float4*)(skip + (size_t)node * stride))[tid];
        acc.x += sv.x; acc.y += sv.y; acc.z += sv.z; acc.w += sv.w;
    }
    acc.x = elu_f(acc.x); acc.y = elu_f(acc.y);
    acc.z = elu_f(acc.z); acc.w = elu_f(acc.w);

    __nv_bfloat16 h[4], l[4];
    float vv[4] = {acc.x, acc.y, acc.z, acc.w};
    #pragma unroll
    for (int q = 0; q < 4; q++) {
        h[q] = __float2bfloat16(vv[q]);
        l[q] = __float2bfloat16(vv[q] - __bfloat162float(h[q]));
    }
    *(uint2*)(oh + (size_t)node * HID + tid * 4) = *(uint2*)h;
    *(uint2*)(ol + (size_t)node * HID + tid * 4) = *(uint2*)l;
}

// 726 features, stride 1452, skip at +726, no activation, fp32 out (stride 726)
__global__ void agg726_kernel(const float* __restrict__ src, const float* __restrict__ skip,
                              float* __restrict__ out,
                              const int* __restrict__ offs, const int* __restrict__ csr_src,
                              const float* __restrict__ csr_w) {
    int node = blockIdx.x;
    int tid = threadIdx.x;
    int f0 = tid, f1 = tid + 256, f2 = tid + 512;
    bool v2 = (f2 < F3);
    float a0 = 0.f, a1 = 0.f, a2 = 0.f;
    int beg = offs[node], end = offs[node + 1];
    for (int j = beg; j < end; j++) {
        int s = csr_src[j];
        float w = csr_w[j];
        const float* r = src + (size_t)s * N3;
        a0 = fmaf(w, __ldg(r + f0), a0);
        a1 = fmaf(w, __ldg(r + f1), a1);
        if (v2) a2 = fmaf(w, __ldg(r + f2), a2);
    }
    const float* sk = skip + (size_t)node * N3;
    float* o = out + (size_t)node * F3;
    o[f0] = a0 + sk[f0];
    o[f1] = a1 + sk[f1];
    if (v2) o[f2] = a2 + sk[f2];
}

// ---------------- final mean over 6 heads ---------------------------------------
__global__ void mean_kernel(const float* __restrict__ t, float* __restrict__ out) {
    int i = blockIdx.x * blockDim.x + threadIdx.x;
    if (i < NN * NCLS) {
        int n = i / NCLS, c = i % NCLS;
        const float* r = t + (size_t)n * F3 + c;
        float s = r[0] + r[NCLS] + r[2 * NCLS] + r[3 * NCLS] + r[4 * NCLS] + r[5 * NCLS];
        out[i] = s * (1.0f / 6.0f);
    }
}

// ---------------- launcher -------------------------------------------------------
extern "C" void kernel_launch(void* const* d_in, const int* in_sizes, int n_in,
                              void* d_out, int out_size) {
    const float* X  = (const float*)d_in[0];
    const int*   ei = (const int*)d_in[1];
    const float* W1 = (const float*)d_in[2];
    const float* W2 = (const float*)d_in[3];
    const float* S2 = (const float*)d_in[4];
    const float* W3 = (const float*)d_in[5];
    const float* S3 = (const float*)d_in[6];
    float* out = (float*)d_out;

    const int* row = ei;
    const int* col = ei + NE;

    float *A, *F, *w;
    int *deg, *cur, *offs, *src;
    __nv_bfloat16 *Ah, *Al, *W2h, *W2l, *W3h, *W3l;
    cudaGetSymbolAddress((void**)&A,    g_A);
    cudaGetSymbolAddress((void**)&F,    g_F);
    cudaGetSymbolAddress((void**)&deg,  g_deg);
    cudaGetSymbolAddress((void**)&cur,  g_cursor);
    cudaGetSymbolAddress((void**)&offs, g_offs);
    cudaGetSymbolAddress((void**)&src,  g_src);
    cudaGetSymbolAddress((void**)&w,    g_w);
    cudaGetSymbolAddress((void**)&Ah,   g_Ah);
    cudaGetSymbolAddress((void**)&Al,   g_Al);
    cudaGetSymbolAddress((void**)&W2h,  g_W2h);
    cudaGetSymbolAddress((void**)&W2l,  g_W2l);
    cudaGetSymbolAddress((void**)&W3h,  g_W3h);
    cudaGetSymbolAddress((void**)&W3l,  g_W3l);

    cudaFuncSetAttribute(mma_gemm_kernel, cudaFuncAttributeMaxDynamicSharedMemorySize, MMA_SMEM);

    // 0: weight transpose/split + zero deg/cursor
    prep_kernel<<<8192, 256>>>(W2, S2, W3, S3, W2h, W2l, W3h, W3l, deg, cur);
    // 1: layer-1 GEMM (independent of CSR)
    {
        dim3 grid((NN + 15) / 16, HID / 128);
        gemm1_kernel<<<grid, 128>>>(X, W1, F);
    }
    // 2-4: CSR build
    count_deg_kernel<<<512, 256>>>(col, deg);
    scan_kernel<<<1, 1024>>>(deg, offs);
    fill_csr_kernel<<<512, 256>>>(row, col, offs, cur, deg, src, w);

    // 5: layer-1 agg (+elu +split)  -> Ah/Al
    agg_split_kernel<<<NN, 256>>>(F, nullptr, HID, Ah, Al, offs, src, w);

    // 6: layer 2: A[:, 0:1024] = h1@W2, A[:, 1024:2048] = h1@S2
    {
        dim3 grid(N2 / 128, (NN + 127) / 128);
        mma_gemm_kernel<<<grid, 256, MMA_SMEM>>>(Ah, Al, W2h, W2l, A, NN, N2);
    }
    // 7: layer-2 agg (+skip +elu +split) -> Ah/Al
    agg_split_kernel<<<NN, 256>>>(A, A + HID, N2, Ah, Al, offs, src, w);

    // 8: layer 3: A[:, 0:726] = h2@W3, A[:, 726:1452] = h2@S3
    {
        dim3 grid((N3 + 127) / 128, (NN + 127) / 128);
        mma_gemm_kernel<<<grid, 256, MMA_SMEM>>>(Ah, Al, W3h, W3l, A, NN, N3);
    }
    // 9: layer-3 agg + skip -> F (stride 726)
    agg726_kernel<<<NN, 256>>>(A, A + F3, F, offs, src, w);

    // 10: mean over 6 heads -> out [N, 121]
    mean_kernel<<<(NN * NCLS + 255) / 256, 256>>>(F, out);
}

// round 5
// speedup vs baseline: 1.2704x; 1.2704x over previous
#include <cuda_runtime.h>
#include <cuda_bf16.h>
#include <math.h>
#include <cstdint>

// Problem constants (fixed by the dataset)
#define NN   20000
#define NE   320000
#define DIN  50
#define HID  1024
#define F3   726        // 6 heads * 121 classes
#define NCLS 121
#define N2   2048       // W2 || S2 concatenated output width
#define N3   1452       // W3 || S3 concatenated output width

// ---------------- scratch (device globals) -------------------------------------
__device__ __align__(128) float g_A[(size_t)NN * N2];    // holds both GEMM outputs
__device__ __align__(128) float g_F[(size_t)NN * HID];
__device__ __align__(128) __nv_bfloat16 g_Ah[(size_t)NN * HID];
__device__ __align__(128) __nv_bfloat16 g_Al[(size_t)NN * HID];
__device__ __align__(128) __nv_bfloat16 g_W2h[(size_t)N2 * HID];
__device__ __align__(128) __nv_bfloat16 g_W2l[(size_t)N2 * HID];
__device__ __align__(128) __nv_bfloat16 g_W3h[(size_t)N3 * HID];
__device__ __align__(128) __nv_bfloat16 g_W3l[(size_t)N3 * HID];
__device__ int   g_deg[NN];
__device__ int   g_cursor[NN];
__device__ int   g_offs[NN + 1];
__device__ int   g_src[NE];
__device__ float g_w[NE];

// ================= PTX helpers (portable sm_80+ PTX) ===========================
__device__ __forceinline__ uint32_t smem_u32(const void* p) {
    uint32_t a;
    asm("{ .reg .u64 t; cvta.to.shared.u64 t, %1; cvt.u32.u64 %0, t; }" : "=r"(a) : "l"(p));
    return a;
}
__device__ __forceinline__ void cp16(uint32_t dst, const void* src) {
    uint64_t g = __cvta_generic_to_global(src);
    asm volatile("cp.async.cg.shared.global [%0], [%1], 16;" :: "r"(dst), "l"(g));
}
__device__ __forceinline__ void cp_commit() { asm volatile("cp.async.commit_group;" ::: "memory"); }
template <int N> __device__ __forceinline__ void cp_wait() {
    asm volatile("cp.async.wait_group %0;" :: "n"(N) : "memory");
}
__device__ __forceinline__ void ldm_x4(uint32_t* r, uint32_t addr) {
    asm volatile("ldmatrix.sync.aligned.m8n8.x4.shared.b16 {%0,%1,%2,%3}, [%4];"
                 : "=r"(r[0]), "=r"(r[1]), "=r"(r[2]), "=r"(r[3]) : "r"(addr));
}
__device__ __forceinline__ void mma16816(float* c, const uint32_t* a, const uint32_t* b) {
    asm volatile(
        "mma.sync.aligned.m16n8k16.row.col.f32.bf16.bf16.f32 "
        "{%0,%1,%2,%3}, {%4,%5,%6,%7}, {%8,%9}, {%0,%1,%2,%3};"
        : "+f"(c[0]), "+f"(c[1]), "+f"(c[2]), "+f"(c[3])
        : "r"(a[0]), "r"(a[1]), "r"(a[2]), "r"(a[3]), "r"(b[0]), "r"(b[1]));
}

// ---------------- prep: zero deg/cursor + transpose/split all weights ----------
__global__ void prep_kernel(const float* __restrict__ W2, const float* __restrict__ S2,
                            const float* __restrict__ W3, const float* __restrict__ S3,
                            __nv_bfloat16* __restrict__ W2h, __nv_bfloat16* __restrict__ W2l,
                            __nv_bfloat16* __restrict__ W3h, __nv_bfloat16* __restrict__ W3l,
                            int* __restrict__ deg, int* __restrict__ cur) {
    int i = blockIdx.x * blockDim.x + threadIdx.x;
    int stride = gridDim.x * blockDim.x;
    if (i < NN) { deg[i] = 0; cur[i] = 0; }
    for (int j = i; j < N2 * HID; j += stride) {
        int n = j >> 10, k = j & 1023;
        float v = (n < HID) ? W2[(size_t)k * HID + n] : S2[(size_t)k * HID + (n - HID)];
        __nv_bfloat16 h = __float2bfloat16(v);
        W2h[j] = h;
        W2l[j] = __float2bfloat16(v - __bfloat162float(h));
    }
    for (int j = i; j < N3 * HID; j += stride) {
        int n = j >> 10, k = j & 1023;
        float v = (n < F3) ? W3[(size_t)k * F3 + n] : S3[(size_t)k * F3 + (n - F3)];
        __nv_bfloat16 h = __float2bfloat16(v);
        W3h[j] = h;
        W3l[j] = __float2bfloat16(v - __bfloat162float(h));
    }
}

// ---------------- CSR build ------------------------------------------------------
__global__ void count_deg_kernel(const int* __restrict__ col, int* __restrict__ deg) {
    for (int e = blockIdx.x * blockDim.x + threadIdx.x; e < NE; e += gridDim.x * blockDim.x)
        atomicAdd(&deg[col[e]], 1);
}

// warp-shuffle block scan, 1024 threads, serial over 20 batches
__global__ void scan_kernel(const int* __restrict__ counts, int* __restrict__ offs) {
    __shared__ int wsum[32];
    __shared__ int carry_s;
    int tid = threadIdx.x;
    int wid = tid >> 5, lane = tid & 31;
    if (tid == 0) carry_s = 0;
    __syncthreads();
    for (int base = 0; base < NN; base += 1024) {
        int i = base + tid;
        int v = (i < NN) ? counts[i] : 0;
        int x = v;
        #pragma unroll
        for (int o = 1; o < 32; o <<= 1) {
            int y = __shfl_up_sync(0xFFFFFFFF, x, o);
            if (lane >= o) x += y;
        }
        if (lane == 31) wsum[wid] = x;
        __syncthreads();
        if (wid == 0) {
            int s = wsum[lane];
            #pragma unroll
            for (int o = 1; o < 32; o <<= 1) {
                int y = __shfl_up_sync(0xFFFFFFFF, s, o);
                if (lane >= o) s += y;
            }
            wsum[lane] = s;
        }
        __syncthreads();
        int pre = carry_s + (wid > 0 ? wsum[wid - 1] : 0);
        if (i < NN) offs[i] = pre + x - v;
        __syncthreads();
        if (tid == 0) carry_s += wsum[31];
        __syncthreads();
    }
    if (threadIdx.x == 0) offs[NN] = carry_s;
}

__global__ void fill_csr_kernel(const int* __restrict__ row, const int* __restrict__ col,
                                const int* __restrict__ offs, int* __restrict__ cursor,
                                const int* __restrict__ deg,
                                int* __restrict__ csr_src, float* __restrict__ csr_w) {
    for (int e = blockIdx.x * blockDim.x + threadIdx.x; e < NE; e += gridDim.x * blockDim.x) {
        int r = row[e], c = col[e];
        int p = atomicAdd(&cursor[c], 1);
        int slot = offs[c] + p;
        int dr = deg[r];
        float nr = (dr > 0) ? rsqrtf((float)dr) : 0.0f;
        float nc = rsqrtf((float)deg[c]);
        csr_src[slot] = r;
        csr_w[slot] = nr * nc;
    }
}

// ---------------- layer-1 GEMM: X[N,50] @ W1[50,1024] -------------------------
__global__ void gemm1_kernel(const float* __restrict__ X, const float* __restrict__ W,
                             float* __restrict__ out) {
    __shared__ float Ws[DIN][128];
    __shared__ float Xs[16][DIN + 2];
    int t = threadIdx.x;
    int j0 = blockIdx.y * 128;
    int n0 = blockIdx.x * 16;
    for (int k = 0; k < DIN; k++) Ws[k][t] = W[(size_t)k * HID + j0 + t];
    for (int i = t; i < 16 * DIN; i += 128) {
        int nn = i / DIN, k = i % DIN;
        Xs[nn][k] = (n0 + nn < NN) ? X[(size_t)(n0 + nn) * DIN + k] : 0.0f;
    }
    __syncthreads();
    #pragma unroll 4
    for (int nn = 0; nn < 16; nn++) {
        float acc = 0.f;
        #pragma unroll
        for (int k = 0; k < DIN; k++) acc = fmaf(Xs[nn][k], Ws[k][t], acc);
        if (n0 + nn < NN) out[(size_t)(n0 + nn) * HID + j0 + t] = acc;
    }
}

// ---------------- mma.sync GEMM (KC=32, 2 CTAs/SM) -----------------------------
// C[M, Nn] = A[M, 1024] * B^T, B stored [Nn][1024]. D += Ah*Bh + Ah*Bl + Al*Bh.
// Output split: col c < split -> Cw[r*ld + c], else Cs[r*ld + c - split].
#define KC    32
#define NCH   (HID / KC)        // 32 chunks
#define RS    80                // 64B data + 16B pad per row
#define ARR_B (128 * RS)        // 10240
#define STG_B (4 * ARR_B)       // 40960
#define MMA_SMEM (2 * STG_B)    // 81920 -> 2 CTAs/SM

__device__ __forceinline__ void mma_load_chunk(
    uint32_t st, int k0,
    const __nv_bfloat16* __restrict__ Ah, const __nv_bfloat16* __restrict__ Al,
    const __nv_bfloat16* __restrict__ Bh, const __nv_bfloat16* __restrict__ Bl,
    int tid, int m0, int n0, int M, int Nn) {
    const __nv_bfloat16* bases[4] = {Ah, Al, Bh, Bl};
    #pragma unroll
    for (int j = 0; j < 8; j++) {
        int arr = j >> 1;
        int row = ((j & 1) << 6) + (tid >> 2);   // 0..127
        int seg = tid & 3;
        int g0  = (arr < 2) ? m0 : n0;
        int lim = (arr < 2) ? M  : Nn;
        int grow = g0 + row;
        if (grow < lim) {
            cp16(st + arr * ARR_B + row * RS + seg * 16,
                 bases[arr] + (size_t)grow * HID + k0 + seg * 8);
        }
    }
    cp_commit();
}

__global__ void __launch_bounds__(256, 2) mma_gemm_kernel(
    const __nv_bfloat16* __restrict__ Ah, const __nv_bfloat16* __restrict__ Al,
    const __nv_bfloat16* __restrict__ Bh, const __nv_bfloat16* __restrict__ Bl,
    float* __restrict__ Cw, float* __restrict__ Cs,
    int M, int Nn, int split, int ld) {
    extern __shared__ char smem[];
    uint32_t sb = smem_u32(smem);
    int tid = threadIdx.x;
    int wid = tid >> 5, lane = tid & 31;
    int wm = wid >> 2, wn = wid & 3;             // 2 x 4 warp grid
    int m0 = blockIdx.y * 128;
    int n0 = blockIdx.x * 128;

    // zero-fill rows never cp'd (edge tiles), both stages
    if (m0 + 128 > M || n0 + 128 > Nn) {
        for (int e = tid; e < 1024; e += 256) {
            int s = e >> 9, rem = e & 511;
            int arr = rem >> 7, r = rem & 127;
            bool valid = (arr < 2) ? (m0 + r < M) : (n0 + r < Nn);
            if (!valid) {
                uint32_t a = sb + s * STG_B + arr * ARR_B + r * RS;
                #pragma unroll
                for (int q = 0; q < 4; q++)
                    asm volatile("st.shared.v4.b32 [%0], {%1, %1, %1, %1};"
                                 :: "r"(a + q * 16), "r"(0u) : "memory");
            }
        }
        __syncthreads();
    }

    float acc[4][4][4];
    #pragma unroll
    for (int i = 0; i < 4; i++)
        #pragma unroll
        for (int j = 0; j < 4; j++)
            #pragma unroll
            for (int q = 0; q < 4; q++) acc[i][j][q] = 0.f;

    mma_load_chunk(sb, 0, Ah, Al, Bh, Bl, tid, m0, n0, M, Nn);

    // fragment lane addressing
    int la = lane & 15, lha = (lane >> 4) & 1;                        // A
    int lbr = (lane & 7) + ((lane >> 4) & 1) * 8;                     // B row-in-16
    int lbh = (lane >> 3) & 1;                                        // B k-half

    for (int i = 0; i < NCH; i++) {
        int b = i & 1;
        if (i + 1 < NCH) {
            mma_load_chunk(sb + (b ^ 1) * STG_B, (i + 1) * KC, Ah, Al, Bh, Bl,
                           tid, m0, n0, M, Nn);
            cp_wait<1>();
        } else {
            cp_wait<0>();
        }
        __syncthreads();

        uint32_t st = sb + b * STG_B;
        uint32_t aB = st + (wm * 64) * RS;
        uint32_t bB = st + 2 * ARR_B + (wn * 32) * RS;

        #pragma unroll
        for (int kk = 0; kk < 2; kk++) {
            // B fragments: two paired x4 loads cover 4 n-blocks (hi), two more (lo)
            uint32_t bh[4][2], bl[4][2];
            #pragma unroll
            for (int pair = 0; pair < 2; pair++) {
                uint32_t bd = bB + (pair * 16 + lbr) * RS + lbh * 16 + kk * 32;
                uint32_t r4[4];
                ldm_x4(r4, bd);
                bh[pair * 2][0] = r4[0]; bh[pair * 2][1] = r4[1];
                bh[pair * 2 + 1][0] = r4[2]; bh[pair * 2 + 1][1] = r4[3];
                ldm_x4(r4, bd + ARR_B);
                bl[pair * 2][0] = r4[0]; bl[pair * 2][1] = r4[1];
                bl[pair * 2 + 1][0] = r4[2]; bl[pair * 2 + 1][1] = r4[3];
            }
            // A fragments one im at a time (register pressure)
            #pragma unroll
            for (int im = 0; im < 4; im++) {
                uint32_t ah[4], al[4];
                uint32_t ad = aB + (im * 16 + la) * RS + lha * 16 + kk * 32;
                ldm_x4(ah, ad);
                ldm_x4(al, ad + ARR_B);
                #pragma unroll
                for (int in = 0; in < 4; in++) {
                    mma16816(acc[im][in], ah, bh[in]);
                    mma16816(acc[im][in], ah, bl[in]);
                    mma16816(acc[im][in], al, bh[in]);
                }
            }
        }
        __syncthreads();
    }

    // epilogue: write to split outputs
    int cm = m0 + wm * 64 + (lane >> 2);
    int cn0 = n0 + wn * 32 + (lane & 3) * 2;
    #pragma unroll
    for (int im = 0; im < 4; im++) {
        int r0 = cm + im * 16;
        #pragma unroll
        for (int in = 0; in < 4; in++) {
            int c = cn0 + in * 8;
            if (c < Nn) {   // split and c both even -> pair stays in same half
                float* base0;
                int cc = c;
                if (c < split) base0 = Cw;
                else { base0 = Cs; cc = c - split; }
                if (r0 < M) {
                    float2 v = make_float2(acc[im][in][0], acc[im][in][1]);
                    *(float2*)(base0 + (size_t)r0 * ld + cc) = v;
                }
                if (r0 + 8 < M) {
                    float2 v = make_float2(acc[im][in][2], acc[im][in][3]);
                    *(float2*)(base0 + (size_t)(r0 + 8) * ld + cc) = v;
                }
            }
        }
    }
}

// ---------------- aggregation + elu + bf16 split (fused) ------------------------
__device__ __forceinline__ float elu_f(float x) {
    return x > 0.f ? x : (expf(x) - 1.f);
}

// 1024 features, stride 1024: acc = agg(src) [+ skip], elu, write bf16 hi/lo
__global__ void agg_split_kernel(const float* __restrict__ src, const float* __restrict__ skip,
                                 __nv_bfloat16* __restrict__ oh, __nv_bfloat16* __restrict__ ol,
                                 const int* __restrict__ offs, const int* __restrict__ csr_src,
                                 const float* __restrict__ csr_w) {
    int node = blockIdx.x;
    int tid = threadIdx.x;
    float4 a0 = make_float4(0.f, 0.f, 0.f, 0.f);
    float4 a1 = make_float4(0.f, 0.f, 0.f, 0.f);
    int beg = offs[node], end = offs[node + 1];
    int j = beg;
    for (; j + 1 < end; j += 2) {
        int s0 = csr_src[j], s1 = csr_src[j + 1];
        float w0 = csr_w[j], w1 = csr_w[j + 1];
        float4 v0 = __ldg((const float4*)(src + (size_t)s0 * HID) + tid);
        float4 v1 = __ldg((const float4*)(src + (size_t)s1 * HID) + tid);
        a0.x = fmaf(w0, v0.x, a0.x); a0.y = fmaf(w0, v0.y, a0.y);
        a0.z = fmaf(w0, v0.z, a0.z); a0.w = fmaf(w0, v0.w, a0.w);
        a1.x = fmaf(w1, v1.x, a1.x); a1.y = fmaf(w1, v1.y, a1.y);
        a1.z = fmaf(w1, v1.z, a1.z); a1.w = fmaf(w1, v1.w, a1.w);
    }
    if (j < end) {
        int s0 = csr_src[j];
        float w0 = csr_w[j];
        float4 v0 = __ldg((const float4*)(src + (size_t)s0 * HID) + tid);
        a0.x = fmaf(w0, v0.x, a0.x); a0.y = fmaf(w0, v0.y, a0.y);
        a0.z = fmaf(w0, v0.z, a0.z); a0.w = fmaf(w0, v0.w, a0.w);
    }
    float4 acc = make_float4(a0.x + a1.x, a0.y + a1.y, a0.z + a1.z, a0.w + a1.w);
    if (skip) {
        float4 sv = ((const float4*)(skip + (size_t)node * HID))[tid];
        acc.x += sv.x; acc.y += sv.y; acc.z += sv.z; acc.w += sv.w;
    }
    acc.x = elu_f(acc.x); acc.y = elu_f(acc.y);
    acc.z = elu_f(acc.z); acc.w = elu_f(acc.w);

    __nv_bfloat16 h[4], l[4];
    float vv[4] = {acc.x, acc.y, acc.z, acc.w};
    #pragma unroll
    for (int q = 0; q < 4; q++) {
        h[q] = __float2bfloat16(vv[q]);
        l[q] = __float2bfloat16(vv[q] - __bfloat162float(h[q]));
    }
    *(uint2*)(oh + (size_t)node * HID + tid * 4) = *(uint2*)h;
    *(uint2*)(ol + (size_t)node * HID + tid * 4) = *(uint2*)l;
}

// 726 features, stride 726 src and skip, no activation
__global__ void agg726_kernel(const float* __restrict__ src, const float* __restrict__ skip,
                              float* __restrict__ out,
                              const int* __restrict__ offs, const int* __restrict__ csr_src,
                              const float* __restrict__ csr_w) {
    int node = blockIdx.x;
    int tid = threadIdx.x;
    int f0 = tid, f1 = tid + 256, f2 = tid + 512;
    bool v2 = (f2 < F3);
    float a0 = 0.f, a1 = 0.f, a2 = 0.f;
    float b0 = 0.f, b1 = 0.f, b2 = 0.f;
    int beg = offs[node], end = offs[node + 1];
    int j = beg;
    for (; j + 1 < end; j += 2) {
        int s0 = csr_src[j], s1 = csr_src[j + 1];
        float w0 = csr_w[j], w1 = csr_w[j + 1];
        const float* r0 = src + (size_t)s0 * F3;
        const float* r1 = src + (size_t)s1 * F3;
        a0 = fmaf(w0, __ldg(r0 + f0), a0);
        b0 = fmaf(w1, __ldg(r1 + f0), b0);
        a1 = fmaf(w0, __ldg(r0 + f1), a1);
        b1 = fmaf(w1, __ldg(r1 + f1), b1);
        if (v2) {
            a2 = fmaf(w0, __ldg(r0 + f2), a2);
            b2 = fmaf(w1, __ldg(r1 + f2), b2);
        }
    }
    if (j < end) {
        int s0 = csr_src[j];
        float w0 = csr_w[j];
        const float* r0 = src + (size_t)s0 * F3;
        a0 = fmaf(w0, __ldg(r0 + f0), a0);
        a1 = fmaf(w0, __ldg(r0 + f1), a1);
        if (v2) a2 = fmaf(w0, __ldg(r0 + f2), a2);
    }
    const float* sk = skip + (size_t)node * F3;
    float* o = out + (size_t)node * F3;
    o[f0] = a0 + b0 + sk[f0];
    o[f1] = a1 + b1 + sk[f1];
    if (v2) o[f2] = a2 + b2 + sk[f2];
}

// ---------------- final mean over 6 heads ---------------------------------------
__global__ void mean_kernel(const float* __restrict__ t, float* __restrict__ out) {
    int i = blockIdx.x * blockDim.x + threadIdx.x;
    if (i < NN * NCLS) {
        int n = i / NCLS, c = i % NCLS;
        const float* r = t + (size_t)n * F3 + c;
        float s = r[0] + r[NCLS] + r[2 * NCLS] + r[3 * NCLS] + r[4 * NCLS] + r[5 * NCLS];
        out[i] = s * (1.0f / 6.0f);
    }
}

// ---------------- launcher -------------------------------------------------------
extern "C" void kernel_launch(void* const* d_in, const int* in_sizes, int n_in,
                              void* d_out, int out_size) {
    const float* X  = (const float*)d_in[0];
    const int*   ei = (const int*)d_in[1];
    const float* W1 = (const float*)d_in[2];
    const float* W2 = (const float*)d_in[3];
    const float* S2 = (const float*)d_in[4];
    const float* W3 = (const float*)d_in[5];
    const float* S3 = (const float*)d_in[6];
    float* out = (float*)d_out;

    const int* row = ei;
    const int* col = ei + NE;

    float *A, *F, *w;
    int *deg, *cur, *offs, *src;
    __nv_bfloat16 *Ah, *Al, *W2h, *W2l, *W3h, *W3l;
    cudaGetSymbolAddress((void**)&A,    g_A);
    cudaGetSymbolAddress((void**)&F,    g_F);
    cudaGetSymbolAddress((void**)&deg,  g_deg);
    cudaGetSymbolAddress((void**)&cur,  g_cursor);
    cudaGetSymbolAddress((void**)&offs, g_offs);
    cudaGetSymbolAddress((void**)&src,  g_src);
    cudaGetSymbolAddress((void**)&w,    g_w);
    cudaGetSymbolAddress((void**)&Ah,   g_Ah);
    cudaGetSymbolAddress((void**)&Al,   g_Al);
    cudaGetSymbolAddress((void**)&W2h,  g_W2h);
    cudaGetSymbolAddress((void**)&W2l,  g_W2l);
    cudaGetSymbolAddress((void**)&W3h,  g_W3h);
    cudaGetSymbolAddress((void**)&W3l,  g_W3l);

    cudaFuncSetAttribute(mma_gemm_kernel, cudaFuncAttributeMaxDynamicSharedMemorySize, MMA_SMEM);

    float* Aw2 = A;                          // [NN,1024] stride 1024
    float* As2 = A + (size_t)NN * HID;       // [NN,1024] stride 1024
    float* Aw3 = A;                          // [NN,726] stride 726
    float* As3 = A + (size_t)NN * F3;        // [NN,726] stride 726

    // 0: weight transpose/split + zero deg/cursor
    prep_kernel<<<8192, 256>>>(W2, S2, W3, S3, W2h, W2l, W3h, W3l, deg, cur);
    // 1: layer-1 GEMM (independent of CSR)
    {
        dim3 grid((NN + 15) / 16, HID / 128);
        gemm1_kernel<<<grid, 128>>>(X, W1, F);
    }
    // 2-4: CSR build
    count_deg_kernel<<<512, 256>>>(col, deg);
    scan_kernel<<<1, 1024>>>(deg, offs);
    fill_csr_kernel<<<512, 256>>>(row, col, offs, cur, deg, src, w);

    // 5: layer-1 agg (+elu +split)  -> Ah/Al
    agg_split_kernel<<<NN, 256>>>(F, nullptr, Ah, Al, offs, src, w);

    // 6: layer 2 GEMM: Aw2 = h1@W2, As2 = h1@S2
    {
        dim3 grid(N2 / 128, (NN + 127) / 128);
        mma_gemm_kernel<<<grid, 256, MMA_SMEM>>>(Ah, Al, W2h, W2l, Aw2, As2, NN, N2, HID, HID);
    }
    // 7: layer-2 agg (+skip +elu +split) -> Ah/Al
    agg_split_kernel<<<NN, 256>>>(Aw2, As2, Ah, Al, offs, src, w);

    // 8: layer 3 GEMM: Aw3 = h2@W3, As3 = h2@S3
    {
        dim3 grid((N3 + 127) / 128, (NN + 127) / 128);
        mma_gemm_kernel<<<grid, 256, MMA_SMEM>>>(Ah, Al, W3h, W3l, Aw3, As3, NN, N3, F3, F3);
    }
    // 9: layer-3 agg + skip -> F (stride 726)
    agg726_kernel<<<NN, 256>>>(Aw3, As3, F, offs, src, w);

    // 10: mean over 6 heads -> out [N, 121]
    mean_kernel<<<(NN * NCLS + 255) / 256, 256>>>(F, out);
}

// round 6
// speedup vs baseline: 1.6997x; 1.3379x over previous
#include <cuda_runtime.h>
#include <cuda_bf16.h>
#include <math.h>
#include <cstdint>

// Problem constants
#define NN   20000
#define NE   320000
#define DIN  50
#define HID  1024
#define F3   726
#define NCLS 121
#define K2   2048        // concatenated K for layers 2/3
#define NOUT 128         // padded output width of last GEMM (121 -> 128)

// ---------------- scratch (device globals) -------------------------------------
__device__ __align__(128) __nv_bfloat16 g_A2h[(size_t)NN * K2];  // [g1 | h1] hi
__device__ __align__(128) __nv_bfloat16 g_A2l[(size_t)NN * K2];  // [g1 | h1] lo
__device__ __align__(128) __nv_bfloat16 g_A3h[(size_t)NN * K2];  // [g2 | h2] hi
__device__ __align__(128) __nv_bfloat16 g_A3l[(size_t)NN * K2];  // [g2 | h2] lo
__device__ __align__(128) __nv_bfloat16 g_B2h[(size_t)HID * K2]; // [W2;S2]^T hi
__device__ __align__(128) __nv_bfloat16 g_B2l[(size_t)HID * K2];
__device__ __align__(128) __nv_bfloat16 g_BOh[(size_t)NOUT * K2]; // [W3m;S3m]^T hi
__device__ __align__(128) __nv_bfloat16 g_BOl[(size_t)NOUT * K2];
__device__ __align__(128) float g_g0[(size_t)NN * DIN];
__device__ int   g_deg[NN];
__device__ int   g_cursor[NN];
__device__ int   g_offs[NN + 1];
__device__ int   g_src[NE];
__device__ float g_w[NE];

// ================= PTX helpers =================================================
__device__ __forceinline__ uint32_t smem_u32(const void* p) {
    uint32_t a;
    asm("{ .reg .u64 t; cvta.to.shared.u64 t, %1; cvt.u32.u64 %0, t; }" : "=r"(a) : "l"(p));
    return a;
}
__device__ __forceinline__ void cp16(uint32_t dst, const void* src) {
    uint64_t g = __cvta_generic_to_global(src);
    asm volatile("cp.async.cg.shared.global [%0], [%1], 16;" :: "r"(dst), "l"(g));
}
__device__ __forceinline__ void cp_commit() { asm volatile("cp.async.commit_group;" ::: "memory"); }
template <int N> __device__ __forceinline__ void cp_wait() {
    asm volatile("cp.async.wait_group %0;" :: "n"(N) : "memory");
}
__device__ __forceinline__ void ldm_x4(uint32_t* r, uint32_t addr) {
    asm volatile("ldmatrix.sync.aligned.m8n8.x4.shared.b16 {%0,%1,%2,%3}, [%4];"
                 : "=r"(r[0]), "=r"(r[1]), "=r"(r[2]), "=r"(r[3]) : "r"(addr));
}
__device__ __forceinline__ void mma16816(float* c, const uint32_t* a, const uint32_t* b) {
    asm volatile(
        "mma.sync.aligned.m16n8k16.row.col.f32.bf16.bf16.f32 "
        "{%0,%1,%2,%3}, {%4,%5,%6,%7}, {%8,%9}, {%0,%1,%2,%3};"
        : "+f"(c[0]), "+f"(c[1]), "+f"(c[2]), "+f"(c[3])
        : "r"(a[0]), "r"(a[1]), "r"(a[2]), "r"(a[3]), "r"(b[0]), "r"(b[1]));
}

__device__ __forceinline__ float elu_f(float x) {
    return x > 0.f ? x : (expf(x) - 1.f);
}
__device__ __forceinline__ void split_bf16(float v, __nv_bfloat16& h, __nv_bfloat16& l) {
    h = __float2bfloat16(v);
    l = __float2bfloat16(v - __bfloat162float(h));
}

// ---------------- prep: weights + zero deg/cursor -------------------------------
// B2[n][k] (n<1024, k<2048): k<1024 -> W2[k][n], else S2[k-1024][n]
// BO[n][k] (n<128):  n<121: k<1024 -> mean_h W3[k][h*121+n], else mean_h S3[...]
__global__ void prep_kernel(const float* __restrict__ W2, const float* __restrict__ S2,
                            const float* __restrict__ W3, const float* __restrict__ S3,
                            __nv_bfloat16* __restrict__ B2h, __nv_bfloat16* __restrict__ B2l,
                            __nv_bfloat16* __restrict__ BOh, __nv_bfloat16* __restrict__ BOl,
                            int* __restrict__ deg, int* __restrict__ cur) {
    int i = blockIdx.x * blockDim.x + threadIdx.x;
    int stride = gridDim.x * blockDim.x;
    if (i < NN) { deg[i] = 0; cur[i] = 0; }
    for (int j = i; j < HID * K2; j += stride) {
        int n = j >> 11, k = j & (K2 - 1);
        float v = (k < HID) ? W2[(size_t)k * HID + n] : S2[(size_t)(k - HID) * HID + n];
        __nv_bfloat16 h, l; split_bf16(v, h, l);
        B2h[j] = h; B2l[j] = l;
    }
    for (int j = i; j < NOUT * K2; j += stride) {
        int n = j >> 11, k = j & (K2 - 1);
        float v = 0.f;
        if (n < NCLS) {
            const float* Wp = (k < HID) ? (W3 + (size_t)k * F3) : (S3 + (size_t)(k - HID) * F3);
            #pragma unroll
            for (int hh = 0; hh < 6; hh++) v += Wp[hh * NCLS + n];
            v *= (1.0f / 6.0f);
        }
        __nv_bfloat16 h, l; split_bf16(v, h, l);
        BOh[j] = h; BOl[j] = l;
    }
}

// ---------------- CSR build ------------------------------------------------------
__global__ void count_deg_kernel(const int* __restrict__ col, int* __restrict__ deg) {
    for (int e = blockIdx.x * blockDim.x + threadIdx.x; e < NE; e += gridDim.x * blockDim.x)
        atomicAdd(&deg[col[e]], 1);
}

__global__ void scan_kernel(const int* __restrict__ counts, int* __restrict__ offs) {
    __shared__ int wsum[32];
    __shared__ int carry_s;
    int tid = threadIdx.x;
    int wid = tid >> 5, lane = tid & 31;
    if (tid == 0) carry_s = 0;
    __syncthreads();
    for (int base = 0; base < NN; base += 1024) {
        int i = base + tid;
        int v = (i < NN) ? counts[i] : 0;
        int x = v;
        #pragma unroll
        for (int o = 1; o < 32; o <<= 1) {
            int y = __shfl_up_sync(0xFFFFFFFF, x, o);
            if (lane >= o) x += y;
        }
        if (lane == 31) wsum[wid] = x;
        __syncthreads();
        if (wid == 0) {
            int s = wsum[lane];
            #pragma unroll
            for (int o = 1; o < 32; o <<= 1) {
                int y = __shfl_up_sync(0xFFFFFFFF, s, o);
                if (lane >= o) s += y;
            }
            wsum[lane] = s;
        }
        __syncthreads();
        int pre = carry_s + (wid > 0 ? wsum[wid - 1] : 0);
        if (i < NN) offs[i] = pre + x - v;
        __syncthreads();
        if (tid == 0) carry_s += wsum[31];
        __syncthreads();
    }
    if (threadIdx.x == 0) offs[NN] = carry_s;
}

__global__ void fill_csr_kernel(const int* __restrict__ row, const int* __restrict__ col,
                                const int* __restrict__ offs, int* __restrict__ cursor,
                                const int* __restrict__ deg,
                                int* __restrict__ csr_src, float* __restrict__ csr_w) {
    for (int e = blockIdx.x * blockDim.x + threadIdx.x; e < NE; e += gridDim.x * blockDim.x) {
        int r = row[e], c = col[e];
        int p = atomicAdd(&cursor[c], 1);
        int slot = offs[c] + p;
        int dr = deg[r];
        float nr = (dr > 0) ? rsqrtf((float)dr) : 0.0f;
        float nc = rsqrtf((float)deg[c]);
        csr_src[slot] = r;
        csr_w[slot] = nr * nc;
    }
}

// ---------------- g0 = agg(X), 50 features ---------------------------------------
__global__ void agg0_kernel(const float* __restrict__ X, float* __restrict__ g0,
                            const int* __restrict__ offs, const int* __restrict__ csr_src,
                            const float* __restrict__ csr_w) {
    int node = blockIdx.x;
    int t = threadIdx.x;
    if (t >= DIN) return;
    float a0 = 0.f, a1 = 0.f;
    int beg = offs[node], end = offs[node + 1];
    int j = beg;
    for (; j + 1 < end; j += 2) {
        int s0 = csr_src[j], s1 = csr_src[j + 1];
        float w0 = csr_w[j], w1 = csr_w[j + 1];
        a0 = fmaf(w0, __ldg(X + (size_t)s0 * DIN + t), a0);
        a1 = fmaf(w1, __ldg(X + (size_t)s1 * DIN + t), a1);
    }
    if (j < end)
        a0 = fmaf(csr_w[j], __ldg(X + (size_t)csr_src[j] * DIN + t), a0);
    g0[(size_t)node * DIN + t] = a0 + a1;
}

// ---------------- layer-1 GEMM: h1 = elu(g0 @ W1), split -> A2[:,1024:] ----------
__global__ void gemm1_split_kernel(const float* __restrict__ g0, const float* __restrict__ W,
                                   __nv_bfloat16* __restrict__ Oh, __nv_bfloat16* __restrict__ Ol) {
    __shared__ float Ws[DIN][128];
    __shared__ float Xs[16][DIN + 2];
    int t = threadIdx.x;
    int j0 = blockIdx.y * 128;
    int n0 = blockIdx.x * 16;
    for (int k = 0; k < DIN; k++) Ws[k][t] = W[(size_t)k * HID + j0 + t];
    for (int i = t; i < 16 * DIN; i += 128) {
        int nn = i / DIN, k = i % DIN;
        Xs[nn][k] = (n0 + nn < NN) ? g0[(size_t)(n0 + nn) * DIN + k] : 0.0f;
    }
    __syncthreads();
    #pragma unroll 4
    for (int nn = 0; nn < 16; nn++) {
        float acc = 0.f;
        #pragma unroll
        for (int k = 0; k < DIN; k++) acc = fmaf(Xs[nn][k], Ws[k][t], acc);
        if (n0 + nn < NN) {
            float v = elu_f(acc);
            __nv_bfloat16 h, l; split_bf16(v, h, l);
            size_t o = (size_t)(n0 + nn) * K2 + HID + j0 + t;
            Oh[o] = h; Ol[o] = l;
        }
    }
}

// ---------------- agg on bf16-split features: g = agg(A[:,1024:]) -> A[:,0:1024] --
__device__ __forceinline__ void acc4(float* a, uint2 hv, uint2 lv, float w) {
    float2 h01 = __bfloat1622float2(*(__nv_bfloat162*)&hv.x);
    float2 h23 = __bfloat1622float2(*(__nv_bfloat162*)&hv.y);
    float2 l01 = __bfloat1622float2(*(__nv_bfloat162*)&lv.x);
    float2 l23 = __bfloat1622float2(*(__nv_bfloat162*)&lv.y);
    a[0] = fmaf(w, h01.x + l01.x, a[0]);
    a[1] = fmaf(w, h01.y + l01.y, a[1]);
    a[2] = fmaf(w, h23.x + l23.x, a[2]);
    a[3] = fmaf(w, h23.y + l23.y, a[3]);
}

__global__ void agg_bf16_kernel(__nv_bfloat16* __restrict__ Ah, __nv_bfloat16* __restrict__ Al,
                                const int* __restrict__ offs, const int* __restrict__ csr_src,
                                const float* __restrict__ csr_w) {
    int node = blockIdx.x;
    int tid = threadIdx.x;
    size_t cofs = HID + tid * 4;   // source columns (h part)
    float a0[4] = {0.f, 0.f, 0.f, 0.f};
    float a1[4] = {0.f, 0.f, 0.f, 0.f};
    int beg = offs[node], end = offs[node + 1];
    int j = beg;
    for (; j + 1 < end; j += 2) {
        int s0 = csr_src[j], s1 = csr_src[j + 1];
        float w0 = csr_w[j], w1 = csr_w[j + 1];
        size_t b0 = (size_t)s0 * K2 + cofs;
        size_t b1 = (size_t)s1 * K2 + cofs;
        uint2 h0 = __ldg((const uint2*)(Ah + b0));
        uint2 l0 = __ldg((const uint2*)(Al + b0));
        uint2 h1 = __ldg((const uint2*)(Ah + b1));
        uint2 l1 = __ldg((const uint2*)(Al + b1));
        acc4(a0, h0, l0, w0);
        acc4(a1, h1, l1, w1);
    }
    if (j < end) {
        int s0 = csr_src[j];
        float w0 = csr_w[j];
        size_t b0 = (size_t)s0 * K2 + cofs;
        uint2 h0 = __ldg((const uint2*)(Ah + b0));
        uint2 l0 = __ldg((const uint2*)(Al + b0));
        acc4(a0, h0, l0, w0);
    }
    __nv_bfloat16 hh[4], ll[4];
    #pragma unroll
    for (int q = 0; q < 4; q++) {
        float v = a0[q] + a1[q];
        split_bf16(v, hh[q], ll[q]);
    }
    size_t o = (size_t)node * K2 + tid * 4;   // dest columns (g part)
    *(uint2*)(Ah + o) = *(uint2*)hh;
    *(uint2*)(Al + o) = *(uint2*)ll;
}

// ---------------- mma.sync GEMM (K=2048, KC=32, 2 CTAs/SM) -----------------------
// D = A[M,2048] * B^T (B rows [N][2048]); split: D += Ah*Bh + Ah*Bl + Al*Bh.
// MODE 0: elu + bf16 split -> Oh/Ol at [r*K2 + 1024 + c]
// MODE 1: fp32 -> Out[r*121 + c], c < 121
#define KC    32
#define NCH   (K2 / KC)         // 64 chunks
#define RS    80
#define ARR_B (128 * RS)
#define STG_B (4 * ARR_B)
#define MMA_SMEM (2 * STG_B)    // 81920

__device__ __forceinline__ void mma_load_chunk(
    uint32_t st, int k0,
    const __nv_bfloat16* __restrict__ Ah, const __nv_bfloat16* __restrict__ Al,
    const __nv_bfloat16* __restrict__ Bh, const __nv_bfloat16* __restrict__ Bl,
    int tid, int m0, int n0, int M) {
    const __nv_bfloat16* bases[4] = {Ah, Al, Bh, Bl};
    #pragma unroll
    for (int j = 0; j < 8; j++) {
        int arr = j >> 1;
        int row = ((j & 1) << 6) + (tid >> 2);
        int seg = tid & 3;
        int grow = ((arr < 2) ? m0 : n0) + row;
        if (arr >= 2 || grow < M) {
            cp16(st + arr * ARR_B + row * RS + seg * 16,
                 bases[arr] + (size_t)grow * K2 + k0 + seg * 8);
        }
    }
    cp_commit();
}

template <int MODE>
__global__ void __launch_bounds__(256, 2) mma_gemm_kernel(
    const __nv_bfloat16* __restrict__ Ah, const __nv_bfloat16* __restrict__ Al,
    const __nv_bfloat16* __restrict__ Bh, const __nv_bfloat16* __restrict__ Bl,
    __nv_bfloat16* __restrict__ Oh, __nv_bfloat16* __restrict__ Ol,
    float* __restrict__ Out, int M) {
    extern __shared__ char smem[];
    uint32_t sb = smem_u32(smem);
    int tid = threadIdx.x;
    int wid = tid >> 5, lane = tid & 31;
    int wm = wid >> 2, wn = wid & 3;
    int m0 = blockIdx.y * 128;
    int n0 = blockIdx.x * 128;

    // zero-fill A rows never cp'd (edge m-tiles), both stages
    if (m0 + 128 > M) {
        for (int e = tid; e < 512; e += 256) {
            int s = e >> 8, rem = e & 255;
            int arr = rem >> 7, r = rem & 127;
            if (m0 + r >= M) {
                uint32_t a = sb + s * STG_B + arr * ARR_B + r * RS;
                #pragma unroll
                for (int q = 0; q < 4; q++)
                    asm volatile("st.shared.v4.b32 [%0], {%1, %1, %1, %1};"
                                 :: "r"(a + q * 16), "r"(0u) : "memory");
            }
        }
        __syncthreads();
    }

    float acc[4][4][4];
    #pragma unroll
    for (int i = 0; i < 4; i++)
        #pragma unroll
        for (int j = 0; j < 4; j++)
            #pragma unroll
            for (int q = 0; q < 4; q++) acc[i][j][q] = 0.f;

    mma_load_chunk(sb, 0, Ah, Al, Bh, Bl, tid, m0, n0, M);

    int la = lane & 15, lha = (lane >> 4) & 1;
    int lbr = (lane & 7) + ((lane >> 4) & 1) * 8;
    int lbh = (lane >> 3) & 1;

    for (int i = 0; i < NCH; i++) {
        int b = i & 1;
        if (i + 1 < NCH) {
            mma_load_chunk(sb + (b ^ 1) * STG_B, (i + 1) * KC, Ah, Al, Bh, Bl,
                           tid, m0, n0, M);
            cp_wait<1>();
        } else {
            cp_wait<0>();
        }
        __syncthreads();

        uint32_t st = sb + b * STG_B;
        uint32_t aB = st + (wm * 64) * RS;
        uint32_t bB = st + 2 * ARR_B + (wn * 32) * RS;

        #pragma unroll
        for (int kk = 0; kk < 2; kk++) {
            uint32_t bh[4][2], bl[4][2];
            #pragma unroll
            for (int pair = 0; pair < 2; pair++) {
                uint32_t bd = bB + (pair * 16 + lbr) * RS + lbh * 16 + kk * 32;
                uint32_t r4[4];
                ldm_x4(r4, bd);
                bh[pair * 2][0] = r4[0]; bh[pair * 2][1] = r4[1];
                bh[pair * 2 + 1][0] = r4[2]; bh[pair * 2 + 1][1] = r4[3];
                ldm_x4(r4, bd + ARR_B);
                bl[pair * 2][0] = r4[0]; bl[pair * 2][1] = r4[1];
                bl[pair * 2 + 1][0] = r4[2]; bl[pair * 2 + 1][1] = r4[3];
            }
            #pragma unroll
            for (int im = 0; im < 4; im++) {
                uint32_t ah[4], al[4];
                uint32_t ad = aB + (im * 16 + la) * RS + lha * 16 + kk * 32;
                ldm_x4(ah, ad);
                ldm_x4(al, ad + ARR_B);
                #pragma unroll
                for (int in = 0; in < 4; in++) {
                    mma16816(acc[im][in], ah, bh[in]);
                    mma16816(acc[im][in], ah, bl[in]);
                    mma16816(acc[im][in], al, bh[in]);
                }
            }
        }
        __syncthreads();
    }

    int cm = m0 + wm * 64 + (lane >> 2);
    int cn0 = n0 + wn * 32 + (lane & 3) * 2;
    #pragma unroll
    for (int im = 0; im < 4; im++) {
        #pragma unroll
        for (int half = 0; half < 2; half++) {
            int r = cm + im * 16 + half * 8;
            if (r >= M) continue;
            #pragma unroll
            for (int in = 0; in < 4; in++) {
                int c = cn0 + in * 8;
                float v0 = acc[im][in][half * 2 + 0];
                float v1 = acc[im][in][half * 2 + 1];
                if (MODE == 0) {
                    float e0 = elu_f(v0), e1 = elu_f(v1);
                    __nv_bfloat16 h0, l0, h1, l1;
                    split_bf16(e0, h0, l0);
                    split_bf16(e1, h1, l1);
                    size_t o = (size_t)r * K2 + HID + c;
                    __nv_bfloat162 hp, lp;
                    hp.x = h0; hp.y = h1; lp.x = l0; lp.y = l1;
                    *(__nv_bfloat162*)(Oh + o) = hp;
                    *(__nv_bfloat162*)(Ol + o) = lp;
                } else {
                    if (c < NCLS)     Out[(size_t)r * NCLS + c] = v0;
                    if (c + 1 < NCLS) Out[(size_t)r * NCLS + c + 1] = v1;
                }
            }
        }
    }
}

// ---------------- launcher -------------------------------------------------------
extern "C" void kernel_launch(void* const* d_in, const int* in_sizes, int n_in,
                              void* d_out, int out_size) {
    const float* X  = (const float*)d_in[0];
    const int*   ei = (const int*)d_in[1];
    const float* W1 = (const float*)d_in[2];
    const float* W2 = (const float*)d_in[3];
    const float* S2 = (const float*)d_in[4];
    const float* W3 = (const float*)d_in[5];
    const float* S3 = (const float*)d_in[6];
    float* out = (float*)d_out;

    const int* row = ei;
    const int* col = ei + NE;

    float *g0, *w;
    int *deg, *cur, *offs, *src;
    __nv_bfloat16 *A2h, *A2l, *A3h, *A3l, *B2h, *B2l, *BOh, *BOl;
    cudaGetSymbolAddress((void**)&g0,   g_g0);
    cudaGetSymbolAddress((void**)&deg,  g_deg);
    cudaGetSymbolAddress((void**)&cur,  g_cursor);
    cudaGetSymbolAddress((void**)&offs, g_offs);
    cudaGetSymbolAddress((void**)&src,  g_src);
    cudaGetSymbolAddress((void**)&w,    g_w);
    cudaGetSymbolAddress((void**)&A2h,  g_A2h);
    cudaGetSymbolAddress((void**)&A2l,  g_A2l);
    cudaGetSymbolAddress((void**)&A3h,  g_A3h);
    cudaGetSymbolAddress((void**)&A3l,  g_A3l);
    cudaGetSymbolAddress((void**)&B2h,  g_B2h);
    cudaGetSymbolAddress((void**)&B2l,  g_B2l);
    cudaGetSymbolAddress((void**)&BOh,  g_BOh);
    cudaGetSymbolAddress((void**)&BOl,  g_BOl);

    cudaFuncSetAttribute(mma_gemm_kernel<0>, cudaFuncAttributeMaxDynamicSharedMemorySize, MMA_SMEM);
    cudaFuncSetAttribute(mma_gemm_kernel<1>, cudaFuncAttributeMaxDynamicSharedMemorySize, MMA_SMEM);

    // 0: weight prep (transpose/split/concat/head-mean) + zero deg/cursor
    prep_kernel<<<4096, 256>>>(W2, S2, W3, S3, B2h, B2l, BOh, BOl, deg, cur);
    // 1-3: CSR build
    count_deg_kernel<<<512, 256>>>(col, deg);
    scan_kernel<<<1, 1024>>>(deg, offs);
    fill_csr_kernel<<<512, 256>>>(row, col, offs, cur, deg, src, w);

    // 4: g0 = agg(X) [N,50]
    agg0_kernel<<<NN, 64>>>(X, g0, offs, src, w);

    // 5: h1 = elu(g0@W1) -> split into A2[:, 1024:2048]
    {
        dim3 grid((NN + 15) / 16, HID / 128);
        gemm1_split_kernel<<<grid, 128>>>(g0, W1, A2h, A2l);
    }

    // 6: g1 = agg(h1) -> split into A2[:, 0:1024]
    agg_bf16_kernel<<<NN, 256>>>(A2h, A2l, offs, src, w);

    // 7: h2 = elu([g1,h1] @ [W2;S2]) -> split into A3[:, 1024:2048]
    {
        dim3 grid(HID / 128, (NN + 127) / 128);
        mma_gemm_kernel<0><<<grid, 256, MMA_SMEM>>>(A2h, A2l, B2h, B2l, A3h, A3l, nullptr, NN);
    }

    // 8: g2 = agg(h2) -> split into A3[:, 0:1024]
    agg_bf16_kernel<<<NN, 256>>>(A3h, A3l, offs, src, w);

    // 9: out = [g2,h2] @ [W3m;S3m]  (head-mean folded into weights), write d_out
    {
        dim3 grid(1, (NN + 127) / 128);
        mma_gemm_kernel<1><<<grid, 256, MMA_SMEM>>>(A3h, A3l, BOh, BOl, nullptr, nullptr, out, NN);
    }
}

// round 7
// speedup vs baseline: 1.7684x; 1.0404x over previous
#include <cuda_runtime.h>
#include <cuda_bf16.h>
#include <cuda_fp16.h>
#include <math.h>
#include <cstdint>

// Problem constants
#define NN   20000
#define NE   320000
#define DIN  50
#define HID  1024
#define F3   726
#define NCLS 121
#define K2   2048        // concatenated K for layers 2/3
#define NOUT 128         // padded output width of last GEMM (121 -> 128)

// ---------------- scratch (device globals) -------------------------------------
__device__ __align__(128) __nv_bfloat16 g_A2h[(size_t)NN * K2];  // [g1 | h1] hi
__device__ __align__(128) __nv_bfloat16 g_A2l[(size_t)NN * K2];  // [g1 | h1] lo
__device__ __align__(128) __nv_bfloat16 g_A3h[(size_t)NN * K2];  // [g2 | h2] hi
__device__ __align__(128) __nv_bfloat16 g_A3l[(size_t)NN * K2];  // [g2 | h2] lo
__device__ __align__(128) __half       g_Hf[(size_t)NN * HID];   // agg source (fp16)
__device__ __align__(128) __nv_bfloat16 g_B2h[(size_t)HID * K2]; // [W2;S2]^T hi
__device__ __align__(128) __nv_bfloat16 g_B2l[(size_t)HID * K2];
__device__ __align__(128) __nv_bfloat16 g_BOh[(size_t)NOUT * K2]; // [W3m;S3m]^T hi
__device__ __align__(128) __nv_bfloat16 g_BOl[(size_t)NOUT * K2];
__device__ __align__(128) float g_g0[(size_t)NN * DIN];
__device__ int   g_deg[NN];
__device__ int   g_cursor[NN];
__device__ int   g_offs[NN + 1];
__device__ int   g_src[NE];
__device__ float g_w[NE];

// ================= PTX helpers =================================================
__device__ __forceinline__ uint32_t smem_u32(const void* p) {
    uint32_t a;
    asm("{ .reg .u64 t; cvta.to.shared.u64 t, %1; cvt.u32.u64 %0, t; }" : "=r"(a) : "l"(p));
    return a;
}
__device__ __forceinline__ void cp16(uint32_t dst, const void* src) {
    uint64_t g = __cvta_generic_to_global(src);
    asm volatile("cp.async.cg.shared.global [%0], [%1], 16;" :: "r"(dst), "l"(g));
}
__device__ __forceinline__ void cp_commit() { asm volatile("cp.async.commit_group;" ::: "memory"); }
template <int N> __device__ __forceinline__ void cp_wait() {
    asm volatile("cp.async.wait_group %0;" :: "n"(N) : "memory");
}
__device__ __forceinline__ void ldm_x4(uint32_t* r, uint32_t addr) {
    asm volatile("ldmatrix.sync.aligned.m8n8.x4.shared.b16 {%0,%1,%2,%3}, [%4];"
                 : "=r"(r[0]), "=r"(r[1]), "=r"(r[2]), "=r"(r[3]) : "r"(addr));
}
__device__ __forceinline__ void mma16816(float* c, const uint32_t* a, const uint32_t* b) {
    asm volatile(
        "mma.sync.aligned.m16n8k16.row.col.f32.bf16.bf16.f32 "
        "{%0,%1,%2,%3}, {%4,%5,%6,%7}, {%8,%9}, {%0,%1,%2,%3};"
        : "+f"(c[0]), "+f"(c[1]), "+f"(c[2]), "+f"(c[3])
        : "r"(a[0]), "r"(a[1]), "r"(a[2]), "r"(a[3]), "r"(b[0]), "r"(b[1]));
}

__device__ __forceinline__ float elu_f(float x) {
    return x > 0.f ? x : (expf(x) - 1.f);
}
__device__ __forceinline__ void split_bf16(float v, __nv_bfloat16& h, __nv_bfloat16& l) {
    h = __float2bfloat16(v);
    l = __float2bfloat16(v - __bfloat162float(h));
}

// ---------------- prep: weights + zero deg/cursor -------------------------------
__global__ void prep_kernel(const float* __restrict__ W2, const float* __restrict__ S2,
                            const float* __restrict__ W3, const float* __restrict__ S3,
                            __nv_bfloat16* __restrict__ B2h, __nv_bfloat16* __restrict__ B2l,
                            __nv_bfloat16* __restrict__ BOh, __nv_bfloat16* __restrict__ BOl,
                            int* __restrict__ deg, int* __restrict__ cur) {
    int i = blockIdx.x * blockDim.x + threadIdx.x;
    int stride = gridDim.x * blockDim.x;
    if (i < NN) { deg[i] = 0; cur[i] = 0; }
    for (int j = i; j < HID * K2; j += stride) {
        int n = j >> 11, k = j & (K2 - 1);
        float v = (k < HID) ? W2[(size_t)k * HID + n] : S2[(size_t)(k - HID) * HID + n];
        __nv_bfloat16 h, l; split_bf16(v, h, l);
        B2h[j] = h; B2l[j] = l;
    }
    for (int j = i; j < NOUT * K2; j += stride) {
        int n = j >> 11, k = j & (K2 - 1);
        float v = 0.f;
        if (n < NCLS) {
            const float* Wp = (k < HID) ? (W3 + (size_t)k * F3) : (S3 + (size_t)(k - HID) * F3);
            #pragma unroll
            for (int hh = 0; hh < 6; hh++) v += Wp[hh * NCLS + n];
            v *= (1.0f / 6.0f);
        }
        __nv_bfloat16 h, l; split_bf16(v, h, l);
        BOh[j] = h; BOl[j] = l;
    }
}

// ---------------- CSR build ------------------------------------------------------
__global__ void count_deg_kernel(const int* __restrict__ col, int* __restrict__ deg) {
    for (int e = blockIdx.x * blockDim.x + threadIdx.x; e < NE; e += gridDim.x * blockDim.x)
        atomicAdd(&deg[col[e]], 1);
}

__global__ void scan_kernel(const int* __restrict__ counts, int* __restrict__ offs) {
    __shared__ int wsum[32];
    __shared__ int carry_s;
    int tid = threadIdx.x;
    int wid = tid >> 5, lane = tid & 31;
    if (tid == 0) carry_s = 0;
    __syncthreads();
    for (int base = 0; base < NN; base += 1024) {
        int i = base + tid;
        int v = (i < NN) ? counts[i] : 0;
        int x = v;
        #pragma unroll
        for (int o = 1; o < 32; o <<= 1) {
            int y = __shfl_up_sync(0xFFFFFFFF, x, o);
            if (lane >= o) x += y;
        }
        if (lane == 31) wsum[wid] = x;
        __syncthreads();
        if (wid == 0) {
            int s = wsum[lane];
            #pragma unroll
            for (int o = 1; o < 32; o <<= 1) {
                int y = __shfl_up_sync(0xFFFFFFFF, s, o);
                if (lane >= o) s += y;
            }
            wsum[lane] = s;
        }
        __syncthreads();
        int pre = carry_s + (wid > 0 ? wsum[wid - 1] : 0);
        if (i < NN) offs[i] = pre + x - v;
        __syncthreads();
        if (tid == 0) carry_s += wsum[31];
        __syncthreads();
    }
    if (threadIdx.x == 0) offs[NN] = carry_s;
}

__global__ void fill_csr_kernel(const int* __restrict__ row, const int* __restrict__ col,
                                const int* __restrict__ offs, int* __restrict__ cursor,
                                const int* __restrict__ deg,
                                int* __restrict__ csr_src, float* __restrict__ csr_w) {
    for (int e = blockIdx.x * blockDim.x + threadIdx.x; e < NE; e += gridDim.x * blockDim.x) {
        int r = row[e], c = col[e];
        int p = atomicAdd(&cursor[c], 1);
        int slot = offs[c] + p;
        int dr = deg[r];
        float nr = (dr > 0) ? rsqrtf((float)dr) : 0.0f;
        float nc = rsqrtf((float)deg[c]);
        csr_src[slot] = r;
        csr_w[slot] = nr * nc;
    }
}

// ---------------- g0 = agg(X), 50 features ---------------------------------------
__global__ void agg0_kernel(const float* __restrict__ X, float* __restrict__ g0,
                            const int* __restrict__ offs, const int* __restrict__ csr_src,
                            const float* __restrict__ csr_w) {
    int node = blockIdx.x;
    int t = threadIdx.x;
    if (t >= DIN) return;
    float a0 = 0.f, a1 = 0.f;
    int beg = offs[node], end = offs[node + 1];
    int j = beg;
    for (; j + 1 < end; j += 2) {
        int s0 = csr_src[j], s1 = csr_src[j + 1];
        float w0 = csr_w[j], w1 = csr_w[j + 1];
        a0 = fmaf(w0, __ldg(X + (size_t)s0 * DIN + t), a0);
        a1 = fmaf(w1, __ldg(X + (size_t)s1 * DIN + t), a1);
    }
    if (j < end)
        a0 = fmaf(csr_w[j], __ldg(X + (size_t)csr_src[j] * DIN + t), a0);
    g0[(size_t)node * DIN + t] = a0 + a1;
}

// ---------------- layer-1 GEMM: h1 = elu(g0 @ W1) -> split bf16 + fp16 -----------
__global__ void gemm1_split_kernel(const float* __restrict__ g0, const float* __restrict__ W,
                                   __nv_bfloat16* __restrict__ Oh, __nv_bfloat16* __restrict__ Ol,
                                   __half* __restrict__ Hf) {
    __shared__ float Ws[DIN][128];
    __shared__ float Xs[16][DIN + 2];
    int t = threadIdx.x;
    int j0 = blockIdx.y * 128;
    int n0 = blockIdx.x * 16;
    for (int k = 0; k < DIN; k++) Ws[k][t] = W[(size_t)k * HID + j0 + t];
    for (int i = t; i < 16 * DIN; i += 128) {
        int nn = i / DIN, k = i % DIN;
        Xs[nn][k] = (n0 + nn < NN) ? g0[(size_t)(n0 + nn) * DIN + k] : 0.0f;
    }
    __syncthreads();
    #pragma unroll 4
    for (int nn = 0; nn < 16; nn++) {
        float acc = 0.f;
        #pragma unroll
        for (int k = 0; k < DIN; k++) acc = fmaf(Xs[nn][k], Ws[k][t], acc);
        if (n0 + nn < NN) {
            float v = elu_f(acc);
            __nv_bfloat16 h, l; split_bf16(v, h, l);
            size_t o = (size_t)(n0 + nn) * K2 + HID + j0 + t;
            Oh[o] = h; Ol[o] = l;
            Hf[(size_t)(n0 + nn) * HID + j0 + t] = __float2half(v);
        }
    }
}

// ---------------- agg on fp16 features -> split bf16 g-part ----------------------
// g[node] = sum_j w_j * Hf[src_j]; writes into A[:, 0:1024] (hi/lo).
__global__ void agg_half_kernel(const __half* __restrict__ Hf,
                                __nv_bfloat16* __restrict__ Ah, __nv_bfloat16* __restrict__ Al,
                                const int* __restrict__ offs, const int* __restrict__ csr_src,
                                const float* __restrict__ csr_w) {
    int node = blockIdx.x;
    int tid = threadIdx.x;
    size_t cofs = (size_t)tid * 4;
    float a0[4] = {0.f, 0.f, 0.f, 0.f};
    float a1[4] = {0.f, 0.f, 0.f, 0.f};
    int beg = offs[node], end = offs[node + 1];
    int j = beg;
    for (; j + 1 < end; j += 2) {
        int s0 = csr_src[j], s1 = csr_src[j + 1];
        float w0 = csr_w[j], w1 = csr_w[j + 1];
        uint2 p0 = __ldg((const uint2*)(Hf + (size_t)s0 * HID + cofs));
        uint2 p1 = __ldg((const uint2*)(Hf + (size_t)s1 * HID + cofs));
        float2 v00 = __half22float2(*(__half2*)&p0.x);
        float2 v01 = __half22float2(*(__half2*)&p0.y);
        float2 v10 = __half22float2(*(__half2*)&p1.x);
        float2 v11 = __half22float2(*(__half2*)&p1.y);
        a0[0] = fmaf(w0, v00.x, a0[0]); a0[1] = fmaf(w0, v00.y, a0[1]);
        a0[2] = fmaf(w0, v01.x, a0[2]); a0[3] = fmaf(w0, v01.y, a0[3]);
        a1[0] = fmaf(w1, v10.x, a1[0]); a1[1] = fmaf(w1, v10.y, a1[1]);
        a1[2] = fmaf(w1, v11.x, a1[2]); a1[3] = fmaf(w1, v11.y, a1[3]);
    }
    if (j < end) {
        int s0 = csr_src[j];
        float w0 = csr_w[j];
        uint2 p0 = __ldg((const uint2*)(Hf + (size_t)s0 * HID + cofs));
        float2 v00 = __half22float2(*(__half2*)&p0.x);
        float2 v01 = __half22float2(*(__half2*)&p0.y);
        a0[0] = fmaf(w0, v00.x, a0[0]); a0[1] = fmaf(w0, v00.y, a0[1]);
        a0[2] = fmaf(w0, v01.x, a0[2]); a0[3] = fmaf(w0, v01.y, a0[3]);
    }
    __nv_bfloat16 hh[4], ll[4];
    #pragma unroll
    for (int q = 0; q < 4; q++) {
        float v = a0[q] + a1[q];
        split_bf16(v, hh[q], ll[q]);
    }
    size_t o = (size_t)node * K2 + cofs;   // dest: g part (cols 0:1024)
    *(uint2*)(Ah + o) = *(uint2*)hh;
    *(uint2*)(Al + o) = *(uint2*)ll;
}

// ---------------- mma.sync GEMM (K=2048, KC=32, 2 CTAs/SM) -----------------------
// D = A[M,2048] * B^T; split: D += Ah*Bh + Ah*Bl + Al*Bh.
// MODE 0: elu -> split bf16 at [r*K2+1024+c] + fp16 at Hf[r*1024+c]
// MODE 1: fp32 -> Out[r*121 + c], c < 121
#define KC    32
#define NCH   (K2 / KC)         // 64 chunks
#define RS    80
#define ARR_B (128 * RS)
#define STG_B (4 * ARR_B)
#define MMA_SMEM (2 * STG_B)    // 81920

__device__ __forceinline__ void mma_load_chunk(
    uint32_t st, int k0,
    const __nv_bfloat16* __restrict__ Ah, const __nv_bfloat16* __restrict__ Al,
    const __nv_bfloat16* __restrict__ Bh, const __nv_bfloat16* __restrict__ Bl,
    int tid, int m0, int n0, int M) {
    const __nv_bfloat16* bases[4] = {Ah, Al, Bh, Bl};
    #pragma unroll
    for (int j = 0; j < 8; j++) {
        int arr = j >> 1;
        int row = ((j & 1) << 6) + (tid >> 2);
        int seg = tid & 3;
        int grow = ((arr < 2) ? m0 : n0) + row;
        if (arr >= 2 || grow < M) {
            cp16(st + arr * ARR_B + row * RS + seg * 16,
                 bases[arr] + (size_t)grow * K2 + k0 + seg * 8);
        }
    }
    cp_commit();
}

template <int MODE>
__global__ void __launch_bounds__(256, 2) mma_gemm_kernel(
    const __nv_bfloat16* __restrict__ Ah, const __nv_bfloat16* __restrict__ Al,
    const __nv_bfloat16* __restrict__ Bh, const __nv_bfloat16* __restrict__ Bl,
    __nv_bfloat16* __restrict__ Oh, __nv_bfloat16* __restrict__ Ol,
    __half* __restrict__ Hf, float* __restrict__ Out, int M) {
    extern __shared__ char smem[];
    uint32_t sb = smem_u32(smem);
    int tid = threadIdx.x;
    int wid = tid >> 5, lane = tid & 31;
    int wm = wid >> 2, wn = wid & 3;
    int m0 = blockIdx.y * 128;
    int n0 = blockIdx.x * 128;

    if (m0 + 128 > M) {
        for (int e = tid; e < 512; e += 256) {
            int s = e >> 8, rem = e & 255;
            int arr = rem >> 7, r = rem & 127;
            if (m0 + r >= M) {
                uint32_t a = sb + s * STG_B + arr * ARR_B + r * RS;
                #pragma unroll
                for (int q = 0; q < 4; q++)
                    asm volatile("st.shared.v4.b32 [%0], {%1, %1, %1, %1};"
                                 :: "r"(a + q * 16), "r"(0u) : "memory");
            }
        }
        __syncthreads();
    }

    float acc[4][4][4];
    #pragma unroll
    for (int i = 0; i < 4; i++)
        #pragma unroll
        for (int j = 0; j < 4; j++)
            #pragma unroll
            for (int q = 0; q < 4; q++) acc[i][j][q] = 0.f;

    mma_load_chunk(sb, 0, Ah, Al, Bh, Bl, tid, m0, n0, M);

    int la = lane & 15, lha = (lane >> 4) & 1;
    int lbr = (lane & 7) + ((lane >> 4) & 1) * 8;
    int lbh = (lane >> 3) & 1;

    for (int i = 0; i < NCH; i++) {
        int b = i & 1;
        if (i + 1 < NCH) {
            mma_load_chunk(sb + (b ^ 1) * STG_B, (i + 1) * KC, Ah, Al, Bh, Bl,
                           tid, m0, n0, M);
            cp_wait<1>();
        } else {
            cp_wait<0>();
        }
        __syncthreads();

        uint32_t st = sb + b * STG_B;
        uint32_t aB = st + (wm * 64) * RS;
        uint32_t bB = st + 2 * ARR_B + (wn * 32) * RS;

        #pragma unroll
        for (int kk = 0; kk < 2; kk++) {
            uint32_t bh[4][2], bl[4][2];
            #pragma unroll
            for (int pair = 0; pair < 2; pair++) {
                uint32_t bd = bB + (pair * 16 + lbr) * RS + lbh * 16 + kk * 32;
                uint32_t r4[4];
                ldm_x4(r4, bd);
                bh[pair * 2][0] = r4[0]; bh[pair * 2][1] = r4[1];
                bh[pair * 2 + 1][0] = r4[2]; bh[pair * 2 + 1][1] = r4[3];
                ldm_x4(r4, bd + ARR_B);
                bl[pair * 2][0] = r4[0]; bl[pair * 2][1] = r4[1];
                bl[pair * 2 + 1][0] = r4[2]; bl[pair * 2 + 1][1] = r4[3];
            }
            #pragma unroll
            for (int im = 0; im < 4; im++) {
                uint32_t ah[4], al[4];
                uint32_t ad = aB + (im * 16 + la) * RS + lha * 16 + kk * 32;
                ldm_x4(ah, ad);
                ldm_x4(al, ad + ARR_B);
                #pragma unroll
                for (int in = 0; in < 4; in++) {
                    mma16816(acc[im][in], ah, bh[in]);
                    mma16816(acc[im][in], ah, bl[in]);
                    mma16816(acc[im][in], al, bh[in]);
                }
            }
        }
        __syncthreads();
    }

    int cm = m0 + wm * 64 + (lane >> 2);
    int cn0 = n0 + wn * 32 + (lane & 3) * 2;
    #pragma unroll
    for (int im = 0; im < 4; im++) {
        #pragma unroll
        for (int half = 0; half < 2; half++) {
            int r = cm + im * 16 + half * 8;
            if (r >= M) continue;
            #pragma unroll
            for (int in = 0; in < 4; in++) {
                int c = cn0 + in * 8;
                float v0 = acc[im][in][half * 2 + 0];
                float v1 = acc[im][in][half * 2 + 1];
                if (MODE == 0) {
                    float e0 = elu_f(v0), e1 = elu_f(v1);
                    __nv_bfloat16 h0, l0, h1, l1;
                    split_bf16(e0, h0, l0);
                    split_bf16(e1, h1, l1);
                    size_t o = (size_t)r * K2 + HID + c;
                    __nv_bfloat162 hp, lp;
                    hp.x = h0; hp.y = h1; lp.x = l0; lp.y = l1;
                    *(__nv_bfloat162*)(Oh + o) = hp;
                    *(__nv_bfloat162*)(Ol + o) = lp;
                    *(__half2*)(Hf + (size_t)r * HID + c) =
                        __floats2half2_rn(e0, e1);
                } else {
                    if (c < NCLS)     Out[(size_t)r * NCLS + c] = v0;
                    if (c + 1 < NCLS) Out[(size_t)r * NCLS + c + 1] = v1;
                }
            }
        }
    }
}

// ---------------- launcher -------------------------------------------------------
extern "C" void kernel_launch(void* const* d_in, const int* in_sizes, int n_in,
                              void* d_out, int out_size) {
    const float* X  = (const float*)d_in[0];
    const int*   ei = (const int*)d_in[1];
    const float* W1 = (const float*)d_in[2];
    const float* W2 = (const float*)d_in[3];
    const float* S2 = (const float*)d_in[4];
    const float* W3 = (const float*)d_in[5];
    const float* S3 = (const float*)d_in[6];
    float* out = (float*)d_out;

    const int* row = ei;
    const int* col = ei + NE;

    float *g0, *w;
    int *deg, *cur, *offs, *src;
    __half* Hf;
    __nv_bfloat16 *A2h, *A2l, *A3h, *A3l, *B2h, *B2l, *BOh, *BOl;
    cudaGetSymbolAddress((void**)&g0,   g_g0);
    cudaGetSymbolAddress((void**)&deg,  g_deg);
    cudaGetSymbolAddress((void**)&cur,  g_cursor);
    cudaGetSymbolAddress((void**)&offs, g_offs);
    cudaGetSymbolAddress((void**)&src,  g_src);
    cudaGetSymbolAddress((void**)&w,    g_w);
    cudaGetSymbolAddress((void**)&Hf,   g_Hf);
    cudaGetSymbolAddress((void**)&A2h,  g_A2h);
    cudaGetSymbolAddress((void**)&A2l,  g_A2l);
    cudaGetSymbolAddress((void**)&A3h,  g_A3h);
    cudaGetSymbolAddress((void**)&A3l,  g_A3l);
    cudaGetSymbolAddress((void**)&B2h,  g_B2h);
    cudaGetSymbolAddress((void**)&B2l,  g_B2l);
    cudaGetSymbolAddress((void**)&BOh,  g_BOh);
    cudaGetSymbolAddress((void**)&BOl,  g_BOl);

    cudaFuncSetAttribute(mma_gemm_kernel<0>, cudaFuncAttributeMaxDynamicSharedMemorySize, MMA_SMEM);
    cudaFuncSetAttribute(mma_gemm_kernel<1>, cudaFuncAttributeMaxDynamicSharedMemorySize, MMA_SMEM);

    // 0: weight prep + zero deg/cursor
    prep_kernel<<<4096, 256>>>(W2, S2, W3, S3, B2h, B2l, BOh, BOl, deg, cur);
    // 1-3: CSR build
    count_deg_kernel<<<512, 256>>>(col, deg);
    scan_kernel<<<1, 1024>>>(deg, offs);
    fill_csr_kernel<<<512, 256>>>(row, col, offs, cur, deg, src, w);

    // 4: g0 = agg(X) [N,50]
    agg0_kernel<<<NN, 64>>>(X, g0, offs, src, w);

    // 5: h1 = elu(g0@W1) -> A2[:,1024:] split bf16 + Hf fp16
    {
        dim3 grid((NN + 15) / 16, HID / 128);
        gemm1_split_kernel<<<grid, 128>>>(g0, W1, A2h, A2l, Hf);
    }

    // 6: g1 = agg(Hf) -> A2[:, 0:1024]
    agg_half_kernel<<<NN, 256>>>(Hf, A2h, A2l, offs, src, w);

    // 7: h2 = elu([g1,h1] @ [W2;S2]) -> A3[:,1024:] split bf16 + Hf fp16
    {
        dim3 grid(HID / 128, (NN + 127) / 128);
        mma_gemm_kernel<0><<<grid, 256, MMA_SMEM>>>(A2h, A2l, B2h, B2l, A3h, A3l, Hf, nullptr, NN);
    }

    // 8: g2 = agg(Hf) -> A3[:, 0:1024]
    agg_half_kernel<<<NN, 256>>>(Hf, A3h, A3l, offs, src, w);

    // 9: out = [g2,h2] @ [W3m;S3m] -> d_out
    {
        dim3 grid(1, (NN + 127) / 128);
        mma_gemm_kernel<1><<<grid, 256, MMA_SMEM>>>(A3h, A3l, BOh, BOl, nullptr, nullptr, nullptr, out, NN);
    }
}

// round 8
// speedup vs baseline: 2.9193x; 1.6508x over previous
#include <cuda_runtime.h>
#include <cuda_bf16.h>
#include <cuda_fp16.h>
#include <math.h>
#include <cstdint>

// Problem constants
#define NN   20000
#define NE   320000
#define DIN  50
#define HID  1024
#define F3   726
#define NCLS 121
#define K2   2048        // concatenated K for layers 2/3
#define NOUT 128         // padded output width of last GEMM (121 -> 128)

// ---------------- scratch (device globals) -------------------------------------
__device__ __align__(128) __half g_A2[(size_t)NN * K2];   // [g1 | h1] fp16
__device__ __align__(128) __half g_A3[(size_t)NN * K2];   // [g2 | h2] fp16
__device__ __align__(128) __half g_B2[(size_t)HID * K2];  // [W2;S2]^T fp16
__device__ __align__(128) __half g_BO[(size_t)NOUT * K2]; // [W3m;S3m]^T fp16
__device__ __align__(128) float g_g0[(size_t)NN * DIN];
__device__ int   g_deg[NN];
__device__ int   g_cursor[NN];
__device__ int   g_offs[NN + 1];
__device__ int   g_src[NE];
__device__ float g_w[NE];

// ================= PTX helpers =================================================
__device__ __forceinline__ uint32_t smem_u32(const void* p) {
    uint32_t a;
    asm("{ .reg .u64 t; cvta.to.shared.u64 t, %1; cvt.u32.u64 %0, t; }" : "=r"(a) : "l"(p));
    return a;
}
__device__ __forceinline__ void cp16(uint32_t dst, const void* src) {
    uint64_t g = __cvta_generic_to_global(src);
    asm volatile("cp.async.cg.shared.global [%0], [%1], 16;" :: "r"(dst), "l"(g));
}
__device__ __forceinline__ void cp_commit() { asm volatile("cp.async.commit_group;" ::: "memory"); }
template <int N> __device__ __forceinline__ void cp_wait() {
    asm volatile("cp.async.wait_group %0;" :: "n"(N) : "memory");
}
__device__ __forceinline__ void ldm_x4(uint32_t* r, uint32_t addr) {
    asm volatile("ldmatrix.sync.aligned.m8n8.x4.shared.b16 {%0,%1,%2,%3}, [%4];"
                 : "=r"(r[0]), "=r"(r[1]), "=r"(r[2]), "=r"(r[3]) : "r"(addr));
}
__device__ __forceinline__ void mma16816h(float* c, const uint32_t* a, const uint32_t* b) {
    asm volatile(
        "mma.sync.aligned.m16n8k16.row.col.f32.f16.f16.f32 "
        "{%0,%1,%2,%3}, {%4,%5,%6,%7}, {%8,%9}, {%0,%1,%2,%3};"
        : "+f"(c[0]), "+f"(c[1]), "+f"(c[2]), "+f"(c[3])
        : "r"(a[0]), "r"(a[1]), "r"(a[2]), "r"(a[3]), "r"(b[0]), "r"(b[1]));
}

__device__ __forceinline__ float elu_f(float x) {
    return x > 0.f ? x : (expf(x) - 1.f);
}

// ---------------- prep: weights (fp16, transposed, concat, head-mean) ----------
__global__ void prep_kernel(const float* __restrict__ W2, const float* __restrict__ S2,
                            const float* __restrict__ W3, const float* __restrict__ S3,
                            __half* __restrict__ B2, __half* __restrict__ BO,
                            int* __restrict__ deg, int* __restrict__ cur) {
    int i = blockIdx.x * blockDim.x + threadIdx.x;
    int stride = gridDim.x * blockDim.x;
    if (i < NN) { deg[i] = 0; cur[i] = 0; }
    for (int j = i; j < HID * K2; j += stride) {
        int n = j >> 11, k = j & (K2 - 1);
        float v = (k < HID) ? W2[(size_t)k * HID + n] : S2[(size_t)(k - HID) * HID + n];
        B2[j] = __float2half(v);
    }
    for (int j = i; j < NOUT * K2; j += stride) {
        int n = j >> 11, k = j & (K2 - 1);
        float v = 0.f;
        if (n < NCLS) {
            const float* Wp = (k < HID) ? (W3 + (size_t)k * F3) : (S3 + (size_t)(k - HID) * F3);
            #pragma unroll
            for (int hh = 0; hh < 6; hh++) v += Wp[hh * NCLS + n];
            v *= (1.0f / 6.0f);
        }
        BO[j] = __float2half(v);
    }
}

// ---------------- CSR build ------------------------------------------------------
__global__ void count_deg_kernel(const int* __restrict__ col, int* __restrict__ deg) {
    for (int e = blockIdx.x * blockDim.x + threadIdx.x; e < NE; e += gridDim.x * blockDim.x)
        atomicAdd(&deg[col[e]], 1);
}

__global__ void scan_kernel(const int* __restrict__ counts, int* __restrict__ offs) {
    __shared__ int wsum[32];
    __shared__ int carry_s;
    int tid = threadIdx.x;
    int wid = tid >> 5, lane = tid & 31;
    if (tid == 0) carry_s = 0;
    __syncthreads();
    for (int base = 0; base < NN; base += 1024) {
        int i = base + tid;
        int v = (i < NN) ? counts[i] : 0;
        int x = v;
        #pragma unroll
        for (int o = 1; o < 32; o <<= 1) {
            int y = __shfl_up_sync(0xFFFFFFFF, x, o);
            if (lane >= o) x += y;
        }
        if (lane == 31) wsum[wid] = x;
        __syncthreads();
        if (wid == 0) {
            int s = wsum[lane];
            #pragma unroll
            for (int o = 1; o < 32; o <<= 1) {
                int y = __shfl_up_sync(0xFFFFFFFF, s, o);
                if (lane >= o) s += y;
            }
            wsum[lane] = s;
        }
        __syncthreads();
        int pre = carry_s + (wid > 0 ? wsum[wid - 1] : 0);
        if (i < NN) offs[i] = pre + x - v;
        __syncthreads();
        if (tid == 0) carry_s += wsum[31];
        __syncthreads();
    }
    if (threadIdx.x == 0) offs[NN] = carry_s;
}

__global__ void fill_csr_kernel(const int* __restrict__ row, const int* __restrict__ col,
                                const int* __restrict__ offs, int* __restrict__ cursor,
                                const int* __restrict__ deg,
                                int* __restrict__ csr_src, float* __restrict__ csr_w) {
    for (int e = blockIdx.x * blockDim.x + threadIdx.x; e < NE; e += gridDim.x * blockDim.x) {
        int r = row[e], c = col[e];
        int p = atomicAdd(&cursor[c], 1);
        int slot = offs[c] + p;
        int dr = deg[r];
        float nr = (dr > 0) ? rsqrtf((float)dr) : 0.0f;
        float nc = rsqrtf((float)deg[c]);
        csr_src[slot] = r;
        csr_w[slot] = nr * nc;
    }
}

// ---------------- g0 = agg(X), 50 features ---------------------------------------
__global__ void agg0_kernel(const float* __restrict__ X, float* __restrict__ g0,
                            const int* __restrict__ offs, const int* __restrict__ csr_src,
                            const float* __restrict__ csr_w) {
    int node = blockIdx.x;
    int t = threadIdx.x;
    if (t >= DIN) return;
    float a0 = 0.f, a1 = 0.f;
    int beg = offs[node], end = offs[node + 1];
    int j = beg;
    for (; j + 1 < end; j += 2) {
        int s0 = csr_src[j], s1 = csr_src[j + 1];
        float w0 = csr_w[j], w1 = csr_w[j + 1];
        a0 = fmaf(w0, __ldg(X + (size_t)s0 * DIN + t), a0);
        a1 = fmaf(w1, __ldg(X + (size_t)s1 * DIN + t), a1);
    }
    if (j < end)
        a0 = fmaf(csr_w[j], __ldg(X + (size_t)csr_src[j] * DIN + t), a0);
    g0[(size_t)node * DIN + t] = a0 + a1;
}

// ---------------- layer-1 GEMM: h1 = elu(g0 @ W1) -> A2[:,1024:] fp16 ------------
__global__ void gemm1_kernel(const float* __restrict__ g0, const float* __restrict__ W,
                             __half* __restrict__ A) {
    __shared__ float Ws[DIN][128];
    __shared__ float Xs[16][DIN + 2];
    int t = threadIdx.x;
    int j0 = blockIdx.y * 128;
    int n0 = blockIdx.x * 16;
    for (int k = 0; k < DIN; k++) Ws[k][t] = W[(size_t)k * HID + j0 + t];
    for (int i = t; i < 16 * DIN; i += 128) {
        int nn = i / DIN, k = i % DIN;
        Xs[nn][k] = (n0 + nn < NN) ? g0[(size_t)(n0 + nn) * DIN + k] : 0.0f;
    }
    __syncthreads();
    #pragma unroll 4
    for (int nn = 0; nn < 16; nn++) {
        float acc = 0.f;
        #pragma unroll
        for (int k = 0; k < DIN; k++) acc = fmaf(Xs[nn][k], Ws[k][t], acc);
        if (n0 + nn < NN)
            A[(size_t)(n0 + nn) * K2 + HID + j0 + t] = __float2half(elu_f(acc));
    }
}

// ---------------- agg: g = agg(A[:,1024:]) -> A[:,0:1024], fp16 ------------------
__global__ void agg_half_kernel(__half* __restrict__ A,
                                const int* __restrict__ offs, const int* __restrict__ csr_src,
                                const float* __restrict__ csr_w) {
    int node = blockIdx.x;
    int tid = threadIdx.x;
    size_t cofs = HID + (size_t)tid * 4;  // source: h part
    float a0[4] = {0.f, 0.f, 0.f, 0.f};
    float a1[4] = {0.f, 0.f, 0.f, 0.f};
    int beg = offs[node], end = offs[node + 1];
    int j = beg;
    for (; j + 1 < end; j += 2) {
        int s0 = csr_src[j], s1 = csr_src[j + 1];
        float w0 = csr_w[j], w1 = csr_w[j + 1];
        uint2 p0 = __ldg((const uint2*)(A + (size_t)s0 * K2 + cofs));
        uint2 p1 = __ldg((const uint2*)(A + (size_t)s1 * K2 + cofs));
        float2 v00 = __half22float2(*(__half2*)&p0.x);
        float2 v01 = __half22float2(*(__half2*)&p0.y);
        float2 v10 = __half22float2(*(__half2*)&p1.x);
        float2 v11 = __half22float2(*(__half2*)&p1.y);
        a0[0] = fmaf(w0, v00.x, a0[0]); a0[1] = fmaf(w0, v00.y, a0[1]);
        a0[2] = fmaf(w0, v01.x, a0[2]); a0[3] = fmaf(w0, v01.y, a0[3]);
        a1[0] = fmaf(w1, v10.x, a1[0]); a1[1] = fmaf(w1, v10.y, a1[1]);
        a1[2] = fmaf(w1, v11.x, a1[2]); a1[3] = fmaf(w1, v11.y, a1[3]);
    }
    if (j < end) {
        int s0 = csr_src[j];
        float w0 = csr_w[j];
        uint2 p0 = __ldg((const uint2*)(A + (size_t)s0 * K2 + cofs));
        float2 v00 = __half22float2(*(__half2*)&p0.x);
        float2 v01 = __half22float2(*(__half2*)&p0.y);
        a0[0] = fmaf(w0, v00.x, a0[0]); a0[1] = fmaf(w0, v00.y, a0[1]);
        a0[2] = fmaf(w0, v01.x, a0[2]); a0[3] = fmaf(w0, v01.y, a0[3]);
    }
    __half2 o01 = __floats2half2_rn(a0[0] + a1[0], a0[1] + a1[1]);
    __half2 o23 = __floats2half2_rn(a0[2] + a1[2], a0[3] + a1[3]);
    uint2 pk;
    pk.x = *(uint32_t*)&o01;
    pk.y = *(uint32_t*)&o23;
    *(uint2*)(A + (size_t)node * K2 + (size_t)tid * 4) = pk;
}

// ---------------- fp16 mma.sync GEMM (K=2048, KC=64, 2 CTAs/SM) ------------------
// D = A[M,2048] * B^T (B rows [N][2048]), fp16 inputs, fp32 accum.
// MODE 0: elu -> fp16 at O[r*K2 + 1024 + c]
// MODE 1: fp32 -> Out[r*121 + c], c < 121
#define KC    64
#define NCH   (K2 / KC)         // 32 chunks
#define RS    144               // 128B data + 16B pad
#define ARR_B (128 * RS)        // 18432
#define STG_B (2 * ARR_B)       // 36864 (A, B)
#define MMA_SMEM (2 * STG_B)    // 73728 -> 2 CTAs/SM

__device__ __forceinline__ void mma_load_chunk(
    uint32_t st, int k0,
    const __half* __restrict__ A, const __half* __restrict__ B,
    int tid, int m0, int n0, int M) {
    int rrow = tid >> 1;           // 0..127
    int half = tid & 1;            // 64B half of 128B row
    // A
    {
        int grow = m0 + rrow;
        if (grow < M) {
            const __half* gp = A + (size_t)grow * K2 + k0 + half * 32;
            uint32_t sa = st + rrow * RS + half * 64;
            #pragma unroll
            for (int q = 0; q < 4; q++) cp16(sa + q * 16, gp + q * 8);
        }
    }
    // B (rows always valid; zero-padded in prep)
    {
        const __half* gp = B + (size_t)(n0 + rrow) * K2 + k0 + half * 32;
        uint32_t sa = st + ARR_B + rrow * RS + half * 64;
        #pragma unroll
        for (int q = 0; q < 4; q++) cp16(sa + q * 16, gp + q * 8);
    }
    cp_commit();
}

template <int MODE>
__global__ void __launch_bounds__(256, 2) mma_gemm_kernel(
    const __half* __restrict__ Ain, const __half* __restrict__ Bin,
    __half* __restrict__ O, float* __restrict__ Out, int M) {
    extern __shared__ char smem[];
    uint32_t sb = smem_u32(smem);
    int tid = threadIdx.x;
    int wid = tid >> 5, lane = tid & 31;
    int wm = wid >> 2, wn = wid & 3;
    int m0 = blockIdx.y * 128;
    int n0 = blockIdx.x * 128;

    // zero-fill A rows never cp'd (edge m-tiles), both stages
    if (m0 + 128 > M) {
        for (int e = tid; e < 256; e += 256) {
            int s = e >> 7, r = e & 127;
            if (m0 + r >= M) {
                uint32_t a = sb + s * STG_B + r * RS;
                #pragma unroll
                for (int q = 0; q < 8; q++)
                    asm volatile("st.shared.v4.b32 [%0], {%1, %1, %1, %1};"
                                 :: "r"(a + q * 16), "r"(0u) : "memory");
            }
        }
        __syncthreads();
    }

    float acc[4][4][4];
    #pragma unroll
    for (int i = 0; i < 4; i++)
        #pragma unroll
        for (int j = 0; j < 4; j++)
            #pragma unroll
            for (int q = 0; q < 4; q++) acc[i][j][q] = 0.f;

    mma_load_chunk(sb, 0, Ain, Bin, tid, m0, n0, M);

    int la = lane & 15, lha = (lane >> 4) & 1;
    int lbr = (lane & 7) + ((lane >> 4) & 1) * 8;
    int lbh = (lane >> 3) & 1;

    for (int i = 0; i < NCH; i++) {
        int b = i & 1;
        if (i + 1 < NCH) {
            mma_load_chunk(sb + (b ^ 1) * STG_B, (i + 1) * KC, Ain, Bin, tid, m0, n0, M);
            cp_wait<1>();
        } else {
            cp_wait<0>();
        }
        __syncthreads();

        uint32_t st = sb + b * STG_B;
        uint32_t aB = st + (wm * 64) * RS;
        uint32_t bB = st + ARR_B + (wn * 32) * RS;

        #pragma unroll
        for (int kk = 0; kk < 4; kk++) {
            uint32_t bh[4][2];
            #pragma unroll
            for (int pair = 0; pair < 2; pair++) {
                uint32_t bd = bB + (pair * 16 + lbr) * RS + lbh * 16 + kk * 32;
                uint32_t r4[4];
                ldm_x4(r4, bd);
                bh[pair * 2][0] = r4[0]; bh[pair * 2][1] = r4[1];
                bh[pair * 2 + 1][0] = r4[2]; bh[pair * 2 + 1][1] = r4[3];
            }
            #pragma unroll
            for (int im = 0; im < 4; im++) {
                uint32_t ah[4];
                uint32_t ad = aB + (im * 16 + la) * RS + lha * 16 + kk * 32;
                ldm_x4(ah, ad);
                #pragma unroll
                for (int in = 0; in < 4; in++)
                    mma16816h(acc[im][in], ah, bh[in]);
            }
        }
        __syncthreads();
    }

    int cm = m0 + wm * 64 + (lane >> 2);
    int cn0 = n0 + wn * 32 + (lane & 3) * 2;
    #pragma unroll
    for (int im = 0; im < 4; im++) {
        #pragma unroll
        for (int half = 0; half < 2; half++) {
            int r = cm + im * 16 + half * 8;
            if (r >= M) continue;
            #pragma unroll
            for (int in = 0; in < 4; in++) {
                int c = cn0 + in * 8;
                float v0 = acc[im][in][half * 2 + 0];
                float v1 = acc[im][in][half * 2 + 1];
                if (MODE == 0) {
                    __half2 hp = __floats2half2_rn(elu_f(v0), elu_f(v1));
                    *(__half2*)(O + (size_t)r * K2 + HID + c) = hp;
                } else {
                    if (c < NCLS)     Out[(size_t)r * NCLS + c] = v0;
                    if (c + 1 < NCLS) Out[(size_t)r * NCLS + c + 1] = v1;
                }
            }
        }
    }
}

// ---------------- launcher -------------------------------------------------------
extern "C" void kernel_launch(void* const* d_in, const int* in_sizes, int n_in,
                              void* d_out, int out_size) {
    const float* X  = (const float*)d_in[0];
    const int*   ei = (const int*)d_in[1];
    const float* W1 = (const float*)d_in[2];
    const float* W2 = (const float*)d_in[3];
    const float* S2 = (const float*)d_in[4];
    const float* W3 = (const float*)d_in[5];
    const float* S3 = (const float*)d_in[6];
    float* out = (float*)d_out;

    const int* row = ei;
    const int* col = ei + NE;

    float *g0, *w;
    int *deg, *cur, *offs, *src;
    __half *A2, *A3, *B2, *BO;
    cudaGetSymbolAddress((void**)&g0,   g_g0);
    cudaGetSymbolAddress((void**)&deg,  g_deg);
    cudaGetSymbolAddress((void**)&cur,  g_cursor);
    cudaGetSymbolAddress((void**)&offs, g_offs);
    cudaGetSymbolAddress((void**)&src,  g_src);
    cudaGetSymbolAddress((void**)&w,    g_w);
    cudaGetSymbolAddress((void**)&A2,   g_A2);
    cudaGetSymbolAddress((void**)&A3,   g_A3);
    cudaGetSymbolAddress((void**)&B2,   g_B2);
    cudaGetSymbolAddress((void**)&BO,   g_BO);

    cudaFuncSetAttribute(mma_gemm_kernel<0>, cudaFuncAttributeMaxDynamicSharedMemorySize, MMA_SMEM);
    cudaFuncSetAttribute(mma_gemm_kernel<1>, cudaFuncAttributeMaxDynamicSharedMemorySize, MMA_SMEM);

    // 0: weight prep (fp16, transpose/concat/head-mean) + zero deg/cursor
    prep_kernel<<<4096, 256>>>(W2, S2, W3, S3, B2, BO, deg, cur);
    // 1-3: CSR build
    count_deg_kernel<<<512, 256>>>(col, deg);
    scan_kernel<<<1, 1024>>>(deg, offs);
    fill_csr_kernel<<<512, 256>>>(row, col, offs, cur, deg, src, w);

    // 4: g0 = agg(X) [N,50]
    agg0_kernel<<<NN, 64>>>(X, g0, offs, src, w);

    // 5: h1 = elu(g0@W1) -> A2[:,1024:] fp16
    {
        dim3 grid((NN + 15) / 16, HID / 128);
        gemm1_kernel<<<grid, 128>>>(g0, W1, A2);
    }

    // 6: g1 = agg(h1) -> A2[:, 0:1024]
    agg_half_kernel<<<NN, 256>>>(A2, offs, src, w);

    // 7: h2 = elu([g1,h1] @ [W2;S2]) -> A3[:,1024:] fp16
    {
        dim3 grid(HID / 128, (NN + 127) / 128);
        mma_gemm_kernel<0><<<grid, 256, MMA_SMEM>>>(A2, B2, A3, nullptr, NN);
    }

    // 8: g2 = agg(h2) -> A3[:, 0:1024]
    agg_half_kernel<<<NN, 256>>>(A3, offs, src, w);

    // 9: out = [g2,h2] @ [W3m;S3m] -> d_out
    {
        dim3 grid(1, (NN + 127) / 128);
        mma_gemm_kernel<1><<<grid, 256, MMA_SMEM>>>(A3, BO, nullptr, out, NN);
    }
}